// round 1
// baseline (speedup 1.0000x reference)
#include <cuda_runtime.h>
#include <math.h>

// Problem constants
#define BATCH 2
#define SEQ   2048
#define DIM   2048
#define NH    16
#define HDIM  48
#define LAT   256
#define NLH   8
#define ROWS  (BATCH*SEQ)          // 4096
#define QW    (NH*HDIM)            // 768
#define KVW   (NLH*HDIM)           // 384

// ---------------- scratch (no allocations allowed) ----------------
__device__ float g_q  [ROWS * QW];    // [B*T, 768]
__device__ float g_kv [ROWS * LAT];   // [B*T, 256]
__device__ float g_k  [ROWS * KVW];   // [B*T, 384]
__device__ float g_v  [ROWS * KVW];   // [B*T, 384]
__device__ float g_att[ROWS * QW];    // [B*T, 768]

// ---------------- tiled SGEMM: C[M,N] = A[M,K] @ B[K,N] ----------------
// BM=BN=64, BK=16, 256 threads, each thread computes 4x4.
#define BM 64
#define BN 64
#define BK 16
#define APAD 4

__global__ __launch_bounds__(256)
void sgemm64(const float* __restrict__ A, const float* __restrict__ B,
             float* __restrict__ C, int M, int N, int K) {
    __shared__ float As[BK][BM + APAD];   // A stored transposed: As[k][m]
    __shared__ float Bs[BK][BN];

    const int tid = threadIdx.x;
    const int tx  = tid & 15;          // 0..15  (N dir)
    const int ty  = tid >> 4;          // 0..15  (M dir)
    const int row0 = blockIdx.y * BM;
    const int col0 = blockIdx.x * BN;

    // A tile loader: 64 rows x 16 cols -> 256 float4 (one per thread)
    const int arow  = tid >> 2;            // 0..63
    const int acol4 = (tid & 3) * 4;       // 0,4,8,12
    // B tile loader: 16 rows x 64 cols -> 256 float4
    const int brow  = tid >> 4;            // 0..15
    const int bcol4 = (tid & 15) * 4;      // 0..60

    const float* Aptr = A + (size_t)(row0 + arow) * K + acol4;
    const float* Bptr = B + (size_t)brow * N + col0 + bcol4;

    float acc[4][4] = {};

    for (int k0 = 0; k0 < K; k0 += BK) {
        float4 av = *(const float4*)(Aptr + k0);
        As[acol4 + 0][arow] = av.x;
        As[acol4 + 1][arow] = av.y;
        As[acol4 + 2][arow] = av.z;
        As[acol4 + 3][arow] = av.w;
        *(float4*)&Bs[brow][bcol4] = *(const float4*)(Bptr + (size_t)k0 * N);
        __syncthreads();

        #pragma unroll
        for (int kk = 0; kk < BK; kk++) {
            float4 af = *(const float4*)&As[kk][ty * 4];
            float4 bf = *(const float4*)&Bs[kk][tx * 4];
            float a[4] = {af.x, af.y, af.z, af.w};
            float b[4] = {bf.x, bf.y, bf.z, bf.w};
            #pragma unroll
            for (int i = 0; i < 4; i++)
                #pragma unroll
                for (int j = 0; j < 4; j++)
                    acc[i][j] = fmaf(a[i], b[j], acc[i][j]);
        }
        __syncthreads();
    }

    #pragma unroll
    for (int i = 0; i < 4; i++) {
        float4 v = make_float4(acc[i][0], acc[i][1], acc[i][2], acc[i][3]);
        *(float4*)(C + (size_t)(row0 + ty * 4 + i) * N + col0 + tx * 4) = v;
    }
}

// ---------------- RMSNorm over last dim (LAT=256), in place ----------------
__global__ __launch_bounds__(256)
void rmsnorm_k(float* __restrict__ kv, const float* __restrict__ w) {
    const int row = blockIdx.x;
    const int tid = threadIdx.x;
    float v = kv[(size_t)row * LAT + tid];
    __shared__ float red[256];
    red[tid] = v * v;
    __syncthreads();
    #pragma unroll
    for (int s = 128; s > 0; s >>= 1) {
        if (tid < s) red[tid] += red[tid + s];
        __syncthreads();
    }
    float inv = rsqrtf(red[0] * (1.0f / LAT) + 1e-5f);
    kv[(size_t)row * LAT + tid] = v * inv * w[tid];
}

// ---------------- causal flash attention ----------------
// grid: (SEQ/128, BATCH*NH), 128 threads; thread = one query row.
#define QTB 128
#define KTILE 64

__global__ __launch_bounds__(QTB)
void attn_k(const float* __restrict__ q, const float* __restrict__ k,
            const float* __restrict__ v, float* __restrict__ att) {
    const int bh  = blockIdx.y;
    const int b   = bh / NH;
    const int h   = bh % NH;
    const int kvh = h / (NH / NLH);
    const int myq = blockIdx.x * QTB + threadIdx.x;   // query position in [0,SEQ)
    const float scale = 1.0f / sqrtf((float)HDIM);

    __shared__ float Ks[KTILE][HDIM];
    __shared__ float Vs[KTILE][HDIM];

    // q row in registers, pre-scaled
    float4 qr[HDIM / 4];
    {
        const float* qp = q + (((size_t)(b * SEQ + myq)) * NH + h) * HDIM;
        #pragma unroll
        for (int i = 0; i < HDIM / 4; i++) {
            float4 t = *(const float4*)(qp + 4 * i);
            qr[i] = make_float4(t.x * scale, t.y * scale, t.z * scale, t.w * scale);
        }
    }

    float o[HDIM];
    #pragma unroll
    for (int i = 0; i < HDIM; i++) o[i] = 0.0f;
    float m = -1e30f, l = 0.0f;

    const int nk = blockIdx.x * QTB + QTB;   // keys needed by this block (causal)

    for (int kt = 0; kt < nk; kt += KTILE) {
        __syncthreads();   // previous tile fully consumed
        // cooperative load of K/V tile: 64 rows x 12 float4 each
        for (int i = threadIdx.x; i < KTILE * (HDIM / 4); i += QTB) {
            int r  = i / (HDIM / 4);
            int c4 = (i % (HDIM / 4)) * 4;
            size_t base = (((size_t)(b * SEQ + kt + r)) * NLH + kvh) * HDIM + c4;
            *(float4*)&Ks[r][c4] = *(const float4*)(k + base);
            *(float4*)&Vs[r][c4] = *(const float4*)(v + base);
        }
        __syncthreads();

        int jmax = myq - kt + 1;
        if (jmax > KTILE) jmax = KTILE;
        for (int j = 0; j < jmax; j++) {
            float s = 0.0f;
            #pragma unroll
            for (int c = 0; c < HDIM / 4; c++) {
                float4 kk = *(const float4*)&Ks[j][4 * c];
                s = fmaf(qr[c].x, kk.x, s);
                s = fmaf(qr[c].y, kk.y, s);
                s = fmaf(qr[c].z, kk.z, s);
                s = fmaf(qr[c].w, kk.w, s);
            }
            if (s > m) {               // rare: rescale accumulator
                float corr = __expf(m - s);
                m = s;
                l *= corr;
                #pragma unroll
                for (int i = 0; i < HDIM; i++) o[i] *= corr;
            }
            float p = __expf(s - m);
            l += p;
            #pragma unroll
            for (int c = 0; c < HDIM / 4; c++) {
                float4 vv = *(const float4*)&Vs[j][4 * c];
                o[4 * c + 0] = fmaf(p, vv.x, o[4 * c + 0]);
                o[4 * c + 1] = fmaf(p, vv.y, o[4 * c + 1]);
                o[4 * c + 2] = fmaf(p, vv.z, o[4 * c + 2]);
                o[4 * c + 3] = fmaf(p, vv.w, o[4 * c + 3]);
            }
        }
    }

    float inv = 1.0f / l;
    float* op = att + (((size_t)(b * SEQ + myq)) * NH + h) * HDIM;
    #pragma unroll
    for (int c = 0; c < HDIM / 4; c++) {
        float4 r = make_float4(o[4 * c] * inv, o[4 * c + 1] * inv,
                               o[4 * c + 2] * inv, o[4 * c + 3] * inv);
        *(float4*)(op + 4 * c) = r;
    }
}

// ---------------- launch ----------------
extern "C" void kernel_launch(void* const* d_in, const int* in_sizes, int n_in,
                              void* d_out, int out_size) {
    const float* x      = (const float*)d_in[0];
    // d_in[1] = mask (pure causal tril) -- unused
    const float* Wq     = (const float*)d_in[2];
    const float* Wkv    = (const float*)d_in[3];
    const float* w_norm = (const float*)d_in[4];
    const float* Wk     = (const float*)d_in[5];
    const float* Wv     = (const float*)d_in[6];
    const float* Wo     = (const float*)d_in[7];
    float* out = (float*)d_out;

    float *q, *kv, *kk, *vv, *att;
    cudaGetSymbolAddress((void**)&q,   g_q);
    cudaGetSymbolAddress((void**)&kv,  g_kv);
    cudaGetSymbolAddress((void**)&kk,  g_k);
    cudaGetSymbolAddress((void**)&vv,  g_v);
    cudaGetSymbolAddress((void**)&att, g_att);

    dim3 tb(256);

    // q = x @ Wq : [4096,2048]@[2048,768]
    sgemm64<<<dim3(QW / BN, ROWS / BM), tb>>>(x, Wq, q, ROWS, QW, DIM);
    // kv = x @ Wkv : [4096,2048]@[2048,256]
    sgemm64<<<dim3(LAT / BN, ROWS / BM), tb>>>(x, Wkv, kv, ROWS, LAT, DIM);
    // rmsnorm(kv)
    rmsnorm_k<<<ROWS, LAT>>>(kv, w_norm);
    // k = kv @ Wk, v = kv @ Wv : [4096,256]@[256,384]
    sgemm64<<<dim3(KVW / BN, ROWS / BM), tb>>>(kv, Wk, kk, ROWS, KVW, LAT);
    sgemm64<<<dim3(KVW / BN, ROWS / BM), tb>>>(kv, Wv, vv, ROWS, KVW, LAT);
    // attention
    attn_k<<<dim3(SEQ / QTB, BATCH * NH), QTB>>>(q, kk, vv, att);
    // out = att @ Wo : [4096,768]@[768,2048]
    sgemm64<<<dim3(DIM / BN, ROWS / BM), tb>>>(att, Wo, out, ROWS, DIM, QW);
}

// round 3
// speedup vs baseline: 1.4465x; 1.4465x over previous
#include <cuda_runtime.h>
#include <cuda_bf16.h>
#include <math.h>
#include <stdint.h>

// ---------------- problem constants ----------------
#define BATCH 2
#define SEQ   2048
#define DIM   2048
#define NH    16
#define HDIM  48
#define LAT   256
#define NLH   8
#define ROWS  (BATCH*SEQ)          // 4096
#define QW    (NH*HDIM)            // 768
#define KVW   (NLH*HDIM)           // 384

// ---------------- scratch (no allocations allowed) ----------------
__device__ float g_q  [ROWS * QW];
__device__ float g_kv [ROWS * LAT];
__device__ float g_k  [ROWS * KVW];
__device__ float g_v  [ROWS * KVW];
__device__ float g_att[ROWS * QW];

// bf16 split activations
__device__ __nv_bfloat16 g_xh [ROWS * DIM], g_xl [ROWS * DIM];
__device__ __nv_bfloat16 g_kvh[ROWS * LAT], g_kvl[ROWS * LAT];
__device__ __nv_bfloat16 g_ah [ROWS * QW],  g_al [ROWS * QW];
// bf16 split transposed weights  W[K,N] -> Wt[N,K]
__device__ __nv_bfloat16 g_wq_h [QW * DIM],  g_wq_l [QW * DIM];
__device__ __nv_bfloat16 g_wkv_h[LAT * DIM], g_wkv_l[LAT * DIM];
__device__ __nv_bfloat16 g_wk_h [KVW * LAT], g_wk_l [KVW * LAT];
__device__ __nv_bfloat16 g_wv_h [KVW * LAT], g_wv_l [KVW * LAT];
__device__ __nv_bfloat16 g_wo_h [DIM * QW],  g_wo_l [DIM * QW];

// ---------------- helpers ----------------
__device__ __forceinline__ uint32_t smem_u32(const void* p) {
    uint32_t a;
    asm("{ .reg .u64 t; cvta.to.shared.u64 t, %1; cvt.u32.u64 %0, t; }" : "=r"(a) : "l"(p));
    return a;
}

#define CP16(dst, src) \
    asm volatile("cp.async.cg.shared.global [%0], [%1], 16;" :: "r"(dst), "l"(src) : "memory")
#define CP_COMMIT() asm volatile("cp.async.commit_group;" ::: "memory")
#define CP_WAIT0()  asm volatile("cp.async.wait_group 0;" ::: "memory")
#define CP_WAIT1()  asm volatile("cp.async.wait_group 1;" ::: "memory")

__device__ __forceinline__ void mma16816(float* c, const uint32_t* a, const uint32_t* b) {
    asm volatile(
        "mma.sync.aligned.m16n8k16.row.col.f32.bf16.bf16.f32 "
        "{%0,%1,%2,%3}, {%4,%5,%6,%7}, {%8,%9}, {%0,%1,%2,%3};"
        : "+f"(c[0]), "+f"(c[1]), "+f"(c[2]), "+f"(c[3])
        : "r"(a[0]), "r"(a[1]), "r"(a[2]), "r"(a[3]), "r"(b[0]), "r"(b[1]));
}

// ---------------- HMMA bf16x3 GEMM ----------------
// C[M,N](f32) = (Ahi+Alo)[M,K] @ (Bhi+Blo)[N,K]^T   (A row-major K, B row-major K)
// Block tile 128x128x32, 256 threads (warp grid 2Mx4N, warp tile 64x32).
// Smem row = 32 bf16 padded to 40 (80B): word-stride 20 -> conflict-free quad loads.
#define GM 128
#define GN 128
#define GK 32
#define ROWB 80                      // padded row bytes
#define T_A  (128 * ROWB)            // 10240 B per tile
#define OFF_AH 0
#define OFF_AL (T_A)
#define OFF_BH (2*T_A)
#define OFF_BL (3*T_A)
#define STAGE  (4*T_A)               // 40960 B per stage
#define SMEM_GEMM (2*STAGE)          // 81920 B

__device__ __forceinline__ void stage_load(
    const char* Ah, const char* Al, const char* Bh, const char* Bl,
    uint32_t sbase, int tid, int m0, int n0, int k0, int K)
{
    #pragma unroll
    for (int u = 0; u < 2; u++) {
        const int s   = tid * 2 + u;         // 0..511
        const int row = s >> 2;              // 0..127
        const int cc  = s & 3;               // 16B chunk in 64B row
        const uint32_t so = row * ROWB + cc * 16;
        const size_t gA = ((size_t)(m0 + row) * K + k0) * 2 + cc * 16;
        const size_t gB = ((size_t)(n0 + row) * K + k0) * 2 + cc * 16;
        CP16(sbase + OFF_AH + so, Ah + gA);
        CP16(sbase + OFF_AL + so, Al + gA);
        CP16(sbase + OFF_BH + so, Bh + gB);
        CP16(sbase + OFF_BL + so, Bl + gB);
    }
}

__global__ __launch_bounds__(256, 2)
void gemm_mma(const __nv_bfloat16* __restrict__ Ahi, const __nv_bfloat16* __restrict__ Alo,
              const __nv_bfloat16* __restrict__ Bhi, const __nv_bfloat16* __restrict__ Blo,
              float* __restrict__ C, int K, int N) {
    extern __shared__ char smem[];
    const uint32_t sb = smem_u32(smem);
    const int tid = threadIdx.x;
    const int wid = tid >> 5, lid = tid & 31;
    const int wm = wid >> 2;           // 0..1
    const int wn = wid & 3;            // 0..3
    const int g = lid >> 2, ctg = lid & 3;
    const int m0 = blockIdx.y * GM;
    const int n0 = blockIdx.x * GN;

    float acc[4][4][4];
    #pragma unroll
    for (int i = 0; i < 4; i++)
        #pragma unroll
        for (int j = 0; j < 4; j++)
            #pragma unroll
            for (int t = 0; t < 4; t++) acc[i][j][t] = 0.0f;

    const int nch = K / GK;
    stage_load((const char*)Ahi, (const char*)Alo, (const char*)Bhi, (const char*)Blo,
               sb, tid, m0, n0, 0, K);
    CP_COMMIT();

    for (int c = 0; c < nch; c++) {
        if (c + 1 < nch) {
            stage_load((const char*)Ahi, (const char*)Alo, (const char*)Bhi, (const char*)Blo,
                       sb + ((c + 1) & 1) * STAGE, tid, m0, n0, (c + 1) * GK, K);
            CP_COMMIT();
            CP_WAIT1();
        } else {
            CP_WAIT0();
        }
        __syncthreads();

        const char* sAh = smem + (c & 1) * STAGE + OFF_AH;
        const char* sAl = smem + (c & 1) * STAGE + OFF_AL;
        const char* sBh = smem + (c & 1) * STAGE + OFF_BH;
        const char* sBl = smem + (c & 1) * STAGE + OFF_BL;

        #pragma unroll
        for (int ks = 0; ks < 2; ks++) {
            uint32_t bh[4][2], bl[4][2];
            #pragma unroll
            for (int j = 0; j < 4; j++) {
                const uint32_t bo = (wn * 32 + j * 8 + g) * ROWB + ctg * 4 + ks * 32;
                bh[j][0] = *(const uint32_t*)(sBh + bo);
                bh[j][1] = *(const uint32_t*)(sBh + bo + 16);
                bl[j][0] = *(const uint32_t*)(sBl + bo);
                bl[j][1] = *(const uint32_t*)(sBl + bo + 16);
            }
            #pragma unroll
            for (int i = 0; i < 4; i++) {
                const uint32_t ao = (wm * 64 + i * 16 + g) * ROWB + ctg * 4 + ks * 32;
                uint32_t ah[4], al[4];
                ah[0] = *(const uint32_t*)(sAh + ao);
                ah[1] = *(const uint32_t*)(sAh + ao + 8 * ROWB);
                ah[2] = *(const uint32_t*)(sAh + ao + 16);
                ah[3] = *(const uint32_t*)(sAh + ao + 8 * ROWB + 16);
                al[0] = *(const uint32_t*)(sAl + ao);
                al[1] = *(const uint32_t*)(sAl + ao + 8 * ROWB);
                al[2] = *(const uint32_t*)(sAl + ao + 16);
                al[3] = *(const uint32_t*)(sAl + ao + 8 * ROWB + 16);
                #pragma unroll
                for (int j = 0; j < 4; j++) {
                    mma16816(acc[i][j], ah, bh[j]);
                    mma16816(acc[i][j], ah, bl[j]);
                    mma16816(acc[i][j], al, bh[j]);
                }
            }
        }
        __syncthreads();
    }

    // epilogue: direct global stores
    #pragma unroll
    for (int i = 0; i < 4; i++) {
        const int r0 = m0 + wm * 64 + i * 16 + g;
        #pragma unroll
        for (int j = 0; j < 4; j++) {
            const int c0 = n0 + wn * 32 + j * 8 + ctg * 2;
            float2 v0 = make_float2(acc[i][j][0], acc[i][j][1]);
            float2 v1 = make_float2(acc[i][j][2], acc[i][j][3]);
            *(float2*)(C + (size_t)r0 * N + c0)       = v0;
            *(float2*)(C + (size_t)(r0 + 8) * N + c0) = v1;
        }
    }
}

// ---------------- fp32 -> bf16 hi/lo split (activations) ----------------
__global__ __launch_bounds__(256)
void split_act(const float* __restrict__ in, __nv_bfloat16* __restrict__ hi,
               __nv_bfloat16* __restrict__ lo, int n4) {
    int i = blockIdx.x * 256 + threadIdx.x;
    if (i >= n4) return;
    float4 v = ((const float4*)in)[i];
    __nv_bfloat16 h0 = __float2bfloat16(v.x);
    __nv_bfloat16 h1 = __float2bfloat16(v.y);
    __nv_bfloat16 h2 = __float2bfloat16(v.z);
    __nv_bfloat16 h3 = __float2bfloat16(v.w);
    __nv_bfloat16 l0 = __float2bfloat16(v.x - __bfloat162float(h0));
    __nv_bfloat16 l1 = __float2bfloat16(v.y - __bfloat162float(h1));
    __nv_bfloat16 l2 = __float2bfloat16(v.z - __bfloat162float(h2));
    __nv_bfloat16 l3 = __float2bfloat16(v.w - __bfloat162float(h3));
    __nv_bfloat162 hh0; hh0.x = h0; hh0.y = h1;
    __nv_bfloat162 hh1; hh1.x = h2; hh1.y = h3;
    __nv_bfloat162 ll0; ll0.x = l0; ll0.y = l1;
    __nv_bfloat162 ll1; ll1.x = l2; ll1.y = l3;
    ((__nv_bfloat162*)hi)[2 * i]     = hh0;
    ((__nv_bfloat162*)hi)[2 * i + 1] = hh1;
    ((__nv_bfloat162*)lo)[2 * i]     = ll0;
    ((__nv_bfloat162*)lo)[2 * i + 1] = ll1;
}

// ---------------- W[K,N] fp32 -> Wt[N,K] bf16 hi/lo ----------------
__global__ __launch_bounds__(256)
void transpose_split(const float* __restrict__ W, __nv_bfloat16* __restrict__ th,
                     __nv_bfloat16* __restrict__ tl, int K, int N) {
    __shared__ float ts[32][33];
    const int tx = threadIdx.x;
    const int ty = threadIdx.y;
    const int x0 = blockIdx.x * 32;
    const int y0 = blockIdx.y * 32;
    #pragma unroll
    for (int j = ty; j < 32; j += 8)
        ts[j][tx] = W[(size_t)(y0 + j) * N + x0 + tx];
    __syncthreads();
    #pragma unroll
    for (int j = ty; j < 32; j += 8) {
        float v = ts[tx][j];
        __nv_bfloat16 h = __float2bfloat16(v);
        __nv_bfloat16 l = __float2bfloat16(v - __bfloat162float(h));
        size_t o = (size_t)(x0 + j) * K + y0 + tx;
        th[o] = h;
        tl[o] = l;
    }
}

// ---------------- RMSNorm over last dim (LAT=256), in place ----------------
__global__ __launch_bounds__(256)
void rmsnorm_k(float* __restrict__ kv, const float* __restrict__ w) {
    const int row = blockIdx.x;
    const int tid = threadIdx.x;
    float v = kv[(size_t)row * LAT + tid];
    __shared__ float red[256];
    red[tid] = v * v;
    __syncthreads();
    #pragma unroll
    for (int s = 128; s > 0; s >>= 1) {
        if (tid < s) red[tid] += red[tid + s];
        __syncthreads();
    }
    float inv = rsqrtf(red[0] * (1.0f / LAT) + 1e-5f);
    kv[(size_t)row * LAT + tid] = v * inv * w[tid];
}

// ---------------- causal flash attention (1 thread = 1 query row) ----------------
#define QTB 128
#define KTILE 64

__global__ __launch_bounds__(QTB)
void attn_k(const float* __restrict__ q, const float* __restrict__ k,
            const float* __restrict__ v, float* __restrict__ att) {
    const int bh  = blockIdx.y;
    const int b   = bh / NH;
    const int h   = bh % NH;
    const int kvh = h / (NH / NLH);
    const int myq = blockIdx.x * QTB + threadIdx.x;
    const float scale = 1.0f / sqrtf((float)HDIM);

    __shared__ float Ks[KTILE][HDIM];
    __shared__ float Vs[KTILE][HDIM];

    float4 qr[HDIM / 4];
    {
        const float* qp = q + (((size_t)(b * SEQ + myq)) * NH + h) * HDIM;
        #pragma unroll
        for (int i = 0; i < HDIM / 4; i++) {
            float4 t = *(const float4*)(qp + 4 * i);
            qr[i] = make_float4(t.x * scale, t.y * scale, t.z * scale, t.w * scale);
        }
    }

    float o[HDIM];
    #pragma unroll
    for (int i = 0; i < HDIM; i++) o[i] = 0.0f;
    float m = -1e30f, l = 0.0f;

    const int nk = blockIdx.x * QTB + QTB;

    for (int kt = 0; kt < nk; kt += KTILE) {
        __syncthreads();
        for (int i = threadIdx.x; i < KTILE * (HDIM / 4); i += QTB) {
            int r  = i / (HDIM / 4);
            int c4 = (i % (HDIM / 4)) * 4;
            size_t base = (((size_t)(b * SEQ + kt + r)) * NLH + kvh) * HDIM + c4;
            *(float4*)&Ks[r][c4] = *(const float4*)(k + base);
            *(float4*)&Vs[r][c4] = *(const float4*)(v + base);
        }
        __syncthreads();

        int jmax = myq - kt + 1;
        if (jmax > KTILE) jmax = KTILE;
        for (int j = 0; j < jmax; j++) {
            float s0 = 0.f, s1 = 0.f, s2 = 0.f, s3 = 0.f;
            #pragma unroll
            for (int c = 0; c < HDIM / 4; c += 4) {
                float4 k0 = *(const float4*)&Ks[j][4 * c];
                float4 k1 = *(const float4*)&Ks[j][4 * c + 4];
                float4 k2 = *(const float4*)&Ks[j][4 * c + 8];
                float4 k3 = *(const float4*)&Ks[j][4 * c + 12];
                s0 = fmaf(qr[c].x, k0.x, s0); s0 = fmaf(qr[c].y, k0.y, s0);
                s0 = fmaf(qr[c].z, k0.z, s0); s0 = fmaf(qr[c].w, k0.w, s0);
                s1 = fmaf(qr[c+1].x, k1.x, s1); s1 = fmaf(qr[c+1].y, k1.y, s1);
                s1 = fmaf(qr[c+1].z, k1.z, s1); s1 = fmaf(qr[c+1].w, k1.w, s1);
                s2 = fmaf(qr[c+2].x, k2.x, s2); s2 = fmaf(qr[c+2].y, k2.y, s2);
                s2 = fmaf(qr[c+2].z, k2.z, s2); s2 = fmaf(qr[c+2].w, k2.w, s2);
                s3 = fmaf(qr[c+3].x, k3.x, s3); s3 = fmaf(qr[c+3].y, k3.y, s3);
                s3 = fmaf(qr[c+3].z, k3.z, s3); s3 = fmaf(qr[c+3].w, k3.w, s3);
            }
            float s = (s0 + s1) + (s2 + s3);
            if (s > m) {
                float corr = __expf(m - s);
                m = s;
                l *= corr;
                #pragma unroll
                for (int i = 0; i < HDIM; i++) o[i] *= corr;
            }
            float p = __expf(s - m);
            l += p;
            #pragma unroll
            for (int c = 0; c < HDIM / 4; c++) {
                float4 vv = *(const float4*)&Vs[j][4 * c];
                o[4 * c + 0] = fmaf(p, vv.x, o[4 * c + 0]);
                o[4 * c + 1] = fmaf(p, vv.y, o[4 * c + 1]);
                o[4 * c + 2] = fmaf(p, vv.z, o[4 * c + 2]);
                o[4 * c + 3] = fmaf(p, vv.w, o[4 * c + 3]);
            }
        }
    }

    float inv = 1.0f / l;
    float* op = att + (((size_t)(b * SEQ + myq)) * NH + h) * HDIM;
    #pragma unroll
    for (int c = 0; c < HDIM / 4; c++) {
        float4 r = make_float4(o[4 * c] * inv, o[4 * c + 1] * inv,
                               o[4 * c + 2] * inv, o[4 * c + 3] * inv);
        *(float4*)(op + 4 * c) = r;
    }
}

// ---------------- launch ----------------
extern "C" void kernel_launch(void* const* d_in, const int* in_sizes, int n_in,
                              void* d_out, int out_size) {
    const float* x      = (const float*)d_in[0];
    // d_in[1] = mask (pure causal tril) -- unused
    const float* Wq     = (const float*)d_in[2];
    const float* Wkv    = (const float*)d_in[3];
    const float* w_norm = (const float*)d_in[4];
    const float* Wk     = (const float*)d_in[5];
    const float* Wv     = (const float*)d_in[6];
    const float* Wo     = (const float*)d_in[7];
    float* out = (float*)d_out;

    float *q, *kv, *kk, *vv, *att;
    cudaGetSymbolAddress((void**)&q,   g_q);
    cudaGetSymbolAddress((void**)&kv,  g_kv);
    cudaGetSymbolAddress((void**)&kk,  g_k);
    cudaGetSymbolAddress((void**)&vv,  g_v);
    cudaGetSymbolAddress((void**)&att, g_att);

    __nv_bfloat16 *xh, *xl, *kvh, *kvl, *ah, *al;
    __nv_bfloat16 *wqh, *wql, *wkvh, *wkvl, *wkh, *wkl, *wvh, *wvl, *woh, *wol;
    cudaGetSymbolAddress((void**)&xh,  g_xh);   cudaGetSymbolAddress((void**)&xl,  g_xl);
    cudaGetSymbolAddress((void**)&kvh, g_kvh);  cudaGetSymbolAddress((void**)&kvl, g_kvl);
    cudaGetSymbolAddress((void**)&ah,  g_ah);   cudaGetSymbolAddress((void**)&al,  g_al);
    cudaGetSymbolAddress((void**)&wqh, g_wq_h); cudaGetSymbolAddress((void**)&wql, g_wq_l);
    cudaGetSymbolAddress((void**)&wkvh,g_wkv_h);cudaGetSymbolAddress((void**)&wkvl,g_wkv_l);
    cudaGetSymbolAddress((void**)&wkh, g_wk_h); cudaGetSymbolAddress((void**)&wkl, g_wk_l);
    cudaGetSymbolAddress((void**)&wvh, g_wv_h); cudaGetSymbolAddress((void**)&wvl, g_wv_l);
    cudaGetSymbolAddress((void**)&woh, g_wo_h); cudaGetSymbolAddress((void**)&wol, g_wo_l);

    static int smem_set = 0;
    if (!smem_set) {
        cudaFuncSetAttribute(gemm_mma, cudaFuncAttributeMaxDynamicSharedMemorySize, SMEM_GEMM);
        smem_set = 1;
    }

    dim3 t256(256);
    dim3 ttr(32, 8);

    // weight transposes + splits
    transpose_split<<<dim3(QW / 32,  DIM / 32), ttr>>>(Wq,  wqh,  wql,  DIM, QW);
    transpose_split<<<dim3(LAT / 32, DIM / 32), ttr>>>(Wkv, wkvh, wkvl, DIM, LAT);
    transpose_split<<<dim3(KVW / 32, LAT / 32), ttr>>>(Wk,  wkh,  wkl,  LAT, KVW);
    transpose_split<<<dim3(KVW / 32, LAT / 32), ttr>>>(Wv,  wvh,  wvl,  LAT, KVW);
    transpose_split<<<dim3(DIM / 32, QW / 32),  ttr>>>(Wo,  woh,  wol,  QW,  DIM);

    // x split
    split_act<<<(ROWS * DIM / 4 + 255) / 256, t256>>>(x, xh, xl, ROWS * DIM / 4);

    // q = x @ Wq ; kv = x @ Wkv
    gemm_mma<<<dim3(QW / GN,  ROWS / GM), t256, SMEM_GEMM>>>(xh, xl, wqh,  wql,  q,  DIM, QW);
    gemm_mma<<<dim3(LAT / GN, ROWS / GM), t256, SMEM_GEMM>>>(xh, xl, wkvh, wkvl, kv, DIM, LAT);

    // rmsnorm + split
    rmsnorm_k<<<ROWS, LAT>>>(kv, w_norm);
    split_act<<<(ROWS * LAT / 4 + 255) / 256, t256>>>(kv, kvh, kvl, ROWS * LAT / 4);

    // k = kv @ Wk ; v = kv @ Wv
    gemm_mma<<<dim3(KVW / GN, ROWS / GM), t256, SMEM_GEMM>>>(kvh, kvl, wkh, wkl, kk, LAT, KVW);
    gemm_mma<<<dim3(KVW / GN, ROWS / GM), t256, SMEM_GEMM>>>(kvh, kvl, wvh, wvl, vv, LAT, KVW);

    // attention
    attn_k<<<dim3(SEQ / QTB, BATCH * NH), QTB>>>(q, kk, vv, att);

    // out = att @ Wo
    split_act<<<(ROWS * QW / 4 + 255) / 256, t256>>>(att, ah, al, ROWS * QW / 4);
    gemm_mma<<<dim3(DIM / GN, ROWS / GM), t256, SMEM_GEMM>>>(ah, al, woh, wol, out, QW, DIM);
}

// round 4
// speedup vs baseline: 2.4822x; 1.7160x over previous
#include <cuda_runtime.h>
#include <cuda_bf16.h>
#include <math.h>
#include <stdint.h>

// ---------------- problem constants ----------------
#define BATCH 2
#define SEQ   2048
#define DIM   2048
#define NH    16
#define HDIM  48
#define LAT   256
#define NLH   8
#define ROWS  (BATCH*SEQ)          // 4096
#define QW    (NH*HDIM)            // 768
#define KVW   (NLH*HDIM)           // 384

// ---------------- scratch (no allocations allowed) ----------------
__device__ float g_q  [ROWS * QW];
__device__ float g_kv [ROWS * LAT];
__device__ float g_k  [ROWS * KVW];
__device__ float g_v  [ROWS * KVW];
__device__ float g_att[ROWS * QW];

// bf16 split activations
__device__ __nv_bfloat16 g_xh [ROWS * DIM], g_xl [ROWS * DIM];
__device__ __nv_bfloat16 g_kvh[ROWS * LAT], g_kvl[ROWS * LAT];
__device__ __nv_bfloat16 g_ah [ROWS * QW],  g_al [ROWS * QW];
// bf16 split transposed weights  W[K,N] -> Wt[N,K]
__device__ __nv_bfloat16 g_wq_h [QW * DIM],  g_wq_l [QW * DIM];
__device__ __nv_bfloat16 g_wkv_h[LAT * DIM], g_wkv_l[LAT * DIM];
__device__ __nv_bfloat16 g_wk_h [KVW * LAT], g_wk_l [KVW * LAT];
__device__ __nv_bfloat16 g_wv_h [KVW * LAT], g_wv_l [KVW * LAT];
__device__ __nv_bfloat16 g_wo_h [DIM * QW],  g_wo_l [DIM * QW];
// attention-layout K/V splits:  K: [b][kvh][t][hd]   Vt: [b][kvh][hd][t]
__device__ __nv_bfloat16 g_akh[BATCH*NLH*SEQ*HDIM], g_akl[BATCH*NLH*SEQ*HDIM];
__device__ __nv_bfloat16 g_avh[BATCH*NLH*HDIM*SEQ], g_avl[BATCH*NLH*HDIM*SEQ];

// ---------------- helpers ----------------
__device__ __forceinline__ uint32_t smem_u32(const void* p) {
    uint32_t a;
    asm("{ .reg .u64 t; cvta.to.shared.u64 t, %1; cvt.u32.u64 %0, t; }" : "=r"(a) : "l"(p));
    return a;
}

#define CP16(dst, src) \
    asm volatile("cp.async.cg.shared.global [%0], [%1], 16;" :: "r"(dst), "l"(src) : "memory")
#define CP_COMMIT() asm volatile("cp.async.commit_group;" ::: "memory")
#define CP_WAIT0()  asm volatile("cp.async.wait_group 0;" ::: "memory")
#define CP_WAIT1()  asm volatile("cp.async.wait_group 1;" ::: "memory")

__device__ __forceinline__ void mma16816(float* c, const uint32_t* a, const uint32_t* b) {
    asm volatile(
        "mma.sync.aligned.m16n8k16.row.col.f32.bf16.bf16.f32 "
        "{%0,%1,%2,%3}, {%4,%5,%6,%7}, {%8,%9}, {%0,%1,%2,%3};"
        : "+f"(c[0]), "+f"(c[1]), "+f"(c[2]), "+f"(c[3])
        : "r"(a[0]), "r"(a[1]), "r"(a[2]), "r"(a[3]), "r"(b[0]), "r"(b[1]));
}

// pack two floats to bf16x2 hi and residual lo
__device__ __forceinline__ void split2(float x, float y, uint32_t& h, uint32_t& l) {
    __nv_bfloat162 hb = __floats2bfloat162_rn(x, y);
    h = *reinterpret_cast<uint32_t*>(&hb);
    float hx = __bfloat162float(__low2bfloat16(hb));
    float hy = __bfloat162float(__high2bfloat16(hb));
    __nv_bfloat162 lb = __floats2bfloat162_rn(x - hx, y - hy);
    l = *reinterpret_cast<uint32_t*>(&lb);
}

// ---------------- HMMA bf16x3 GEMM (unchanged from R3) ----------------
#define GM 128
#define GN 128
#define GK 32
#define ROWB 80
#define T_A  (128 * ROWB)
#define OFF_AH 0
#define OFF_AL (T_A)
#define OFF_BH (2*T_A)
#define OFF_BL (3*T_A)
#define STAGE  (4*T_A)
#define SMEM_GEMM (2*STAGE)

__device__ __forceinline__ void stage_load(
    const char* Ah, const char* Al, const char* Bh, const char* Bl,
    uint32_t sbase, int tid, int m0, int n0, int k0, int K)
{
    #pragma unroll
    for (int u = 0; u < 2; u++) {
        const int s   = tid * 2 + u;
        const int row = s >> 2;
        const int cc  = s & 3;
        const uint32_t so = row * ROWB + cc * 16;
        const size_t gA = ((size_t)(m0 + row) * K + k0) * 2 + cc * 16;
        const size_t gB = ((size_t)(n0 + row) * K + k0) * 2 + cc * 16;
        CP16(sbase + OFF_AH + so, Ah + gA);
        CP16(sbase + OFF_AL + so, Al + gA);
        CP16(sbase + OFF_BH + so, Bh + gB);
        CP16(sbase + OFF_BL + so, Bl + gB);
    }
}

__global__ __launch_bounds__(256, 2)
void gemm_mma(const __nv_bfloat16* __restrict__ Ahi, const __nv_bfloat16* __restrict__ Alo,
              const __nv_bfloat16* __restrict__ Bhi, const __nv_bfloat16* __restrict__ Blo,
              float* __restrict__ C, int K, int N) {
    extern __shared__ char smem[];
    const uint32_t sb = smem_u32(smem);
    const int tid = threadIdx.x;
    const int wid = tid >> 5, lid = tid & 31;
    const int wm = wid >> 2;
    const int wn = wid & 3;
    const int g = lid >> 2, ctg = lid & 3;
    const int m0 = blockIdx.y * GM;
    const int n0 = blockIdx.x * GN;

    float acc[4][4][4];
    #pragma unroll
    for (int i = 0; i < 4; i++)
        #pragma unroll
        for (int j = 0; j < 4; j++)
            #pragma unroll
            for (int t = 0; t < 4; t++) acc[i][j][t] = 0.0f;

    const int nch = K / GK;
    stage_load((const char*)Ahi, (const char*)Alo, (const char*)Bhi, (const char*)Blo,
               sb, tid, m0, n0, 0, K);
    CP_COMMIT();

    for (int c = 0; c < nch; c++) {
        if (c + 1 < nch) {
            stage_load((const char*)Ahi, (const char*)Alo, (const char*)Bhi, (const char*)Blo,
                       sb + ((c + 1) & 1) * STAGE, tid, m0, n0, (c + 1) * GK, K);
            CP_COMMIT();
            CP_WAIT1();
        } else {
            CP_WAIT0();
        }
        __syncthreads();

        const char* sAh = smem + (c & 1) * STAGE + OFF_AH;
        const char* sAl = smem + (c & 1) * STAGE + OFF_AL;
        const char* sBh = smem + (c & 1) * STAGE + OFF_BH;
        const char* sBl = smem + (c & 1) * STAGE + OFF_BL;

        #pragma unroll
        for (int ks = 0; ks < 2; ks++) {
            uint32_t bh[4][2], bl[4][2];
            #pragma unroll
            for (int j = 0; j < 4; j++) {
                const uint32_t bo = (wn * 32 + j * 8 + g) * ROWB + ctg * 4 + ks * 32;
                bh[j][0] = *(const uint32_t*)(sBh + bo);
                bh[j][1] = *(const uint32_t*)(sBh + bo + 16);
                bl[j][0] = *(const uint32_t*)(sBl + bo);
                bl[j][1] = *(const uint32_t*)(sBl + bo + 16);
            }
            #pragma unroll
            for (int i = 0; i < 4; i++) {
                const uint32_t ao = (wm * 64 + i * 16 + g) * ROWB + ctg * 4 + ks * 32;
                uint32_t ah[4], al[4];
                ah[0] = *(const uint32_t*)(sAh + ao);
                ah[1] = *(const uint32_t*)(sAh + ao + 8 * ROWB);
                ah[2] = *(const uint32_t*)(sAh + ao + 16);
                ah[3] = *(const uint32_t*)(sAh + ao + 8 * ROWB + 16);
                al[0] = *(const uint32_t*)(sAl + ao);
                al[1] = *(const uint32_t*)(sAl + ao + 8 * ROWB);
                al[2] = *(const uint32_t*)(sAl + ao + 16);
                al[3] = *(const uint32_t*)(sAl + ao + 8 * ROWB + 16);
                #pragma unroll
                for (int j = 0; j < 4; j++) {
                    mma16816(acc[i][j], ah, bh[j]);
                    mma16816(acc[i][j], ah, bl[j]);
                    mma16816(acc[i][j], al, bh[j]);
                }
            }
        }
        __syncthreads();
    }

    #pragma unroll
    for (int i = 0; i < 4; i++) {
        const int r0 = m0 + wm * 64 + i * 16 + g;
        #pragma unroll
        for (int j = 0; j < 4; j++) {
            const int c0 = n0 + wn * 32 + j * 8 + ctg * 2;
            float2 v0 = make_float2(acc[i][j][0], acc[i][j][1]);
            float2 v1 = make_float2(acc[i][j][2], acc[i][j][3]);
            *(float2*)(C + (size_t)r0 * N + c0)       = v0;
            *(float2*)(C + (size_t)(r0 + 8) * N + c0) = v1;
        }
    }
}

// ---------------- fp32 -> bf16 hi/lo split (activations) ----------------
__global__ __launch_bounds__(256)
void split_act(const float* __restrict__ in, __nv_bfloat16* __restrict__ hi,
               __nv_bfloat16* __restrict__ lo, int n4) {
    int i = blockIdx.x * 256 + threadIdx.x;
    if (i >= n4) return;
    float4 v = ((const float4*)in)[i];
    uint32_t h0, l0, h1, l1;
    split2(v.x, v.y, h0, l0);
    split2(v.z, v.w, h1, l1);
    ((uint32_t*)hi)[2 * i]     = h0;
    ((uint32_t*)hi)[2 * i + 1] = h1;
    ((uint32_t*)lo)[2 * i]     = l0;
    ((uint32_t*)lo)[2 * i + 1] = l1;
}

// ---------------- W[K,N] fp32 -> Wt[N,K] bf16 hi/lo ----------------
__global__ __launch_bounds__(256)
void transpose_split(const float* __restrict__ W, __nv_bfloat16* __restrict__ th,
                     __nv_bfloat16* __restrict__ tl, int K, int N) {
    __shared__ float ts[32][33];
    const int tx = threadIdx.x;
    const int ty = threadIdx.y;
    const int x0 = blockIdx.x * 32;
    const int y0 = blockIdx.y * 32;
    #pragma unroll
    for (int j = ty; j < 32; j += 8)
        ts[j][tx] = W[(size_t)(y0 + j) * N + x0 + tx];
    __syncthreads();
    #pragma unroll
    for (int j = ty; j < 32; j += 8) {
        float v = ts[tx][j];
        __nv_bfloat16 h = __float2bfloat16(v);
        __nv_bfloat16 l = __float2bfloat16(v - __bfloat162float(h));
        size_t o = (size_t)(x0 + j) * K + y0 + tx;
        th[o] = h;
        tl[o] = l;
    }
}

// ---------------- RMSNorm over last dim (LAT=256), in place ----------------
__global__ __launch_bounds__(256)
void rmsnorm_k(float* __restrict__ kv, const float* __restrict__ w) {
    const int row = blockIdx.x;
    const int tid = threadIdx.x;
    float v = kv[(size_t)row * LAT + tid];
    __shared__ float red[256];
    red[tid] = v * v;
    __syncthreads();
    #pragma unroll
    for (int s = 128; s > 0; s >>= 1) {
        if (tid < s) red[tid] += red[tid + s];
        __syncthreads();
    }
    float inv = rsqrtf(red[0] * (1.0f / LAT) + 1e-5f);
    kv[(size_t)row * LAT + tid] = v * inv * w[tid];
}

// ---------------- K reorg: g_k fp32 [b*T][kvh*48+hd] -> [b][kvh][t][hd] bf16 hi/lo
__global__ __launch_bounds__(256)
void reorg_k(const float* __restrict__ kin, __nv_bfloat16* __restrict__ kh,
             __nv_bfloat16* __restrict__ kl) {
    const int bkvh = blockIdx.y;            // b*NLH + kvh
    const int b = bkvh / NLH, kvh = bkvh % NLH;
    const int t0 = blockIdx.x * 64;
    for (int i = threadIdx.x; i < 64 * HDIM; i += 256) {
        const int t = i / HDIM, hd = i % HDIM;
        float v = kin[((size_t)(b * SEQ + t0 + t)) * KVW + kvh * HDIM + hd];
        uint32_t fh = __float_as_uint(v) & 0xFFFF0000u;   // truncate? no: round
        // proper round-to-nearest hi:
        __nv_bfloat16 h = __float2bfloat16(v);
        __nv_bfloat16 l = __float2bfloat16(v - __bfloat162float(h));
        (void)fh;
        size_t o = ((size_t)bkvh * SEQ + t0 + t) * HDIM + hd;
        kh[o] = h; kl[o] = l;
    }
}

// ---------------- V reorg + transpose: -> [b][kvh][hd][t] bf16 hi/lo
__global__ __launch_bounds__(256)
void reorg_v(const float* __restrict__ vin, __nv_bfloat16* __restrict__ vh,
             __nv_bfloat16* __restrict__ vl) {
    __shared__ float vs[64][HDIM + 1];
    const int bkvh = blockIdx.y;
    const int b = bkvh / NLH, kvh = bkvh % NLH;
    const int t0 = blockIdx.x * 64;
    for (int i = threadIdx.x; i < 64 * HDIM; i += 256) {
        const int t = i / HDIM, hd = i % HDIM;
        vs[t][hd] = vin[((size_t)(b * SEQ + t0 + t)) * KVW + kvh * HDIM + hd];
    }
    __syncthreads();
    for (int i = threadIdx.x; i < 64 * HDIM; i += 256) {
        const int hd = i / 64, t = i % 64;
        float v = vs[t][hd];
        __nv_bfloat16 h = __float2bfloat16(v);
        __nv_bfloat16 l = __float2bfloat16(v - __bfloat162float(h));
        size_t o = ((size_t)bkvh * HDIM + hd) * SEQ + t0 + t;
        vh[o] = h; vl[o] = l;
    }
}

// ---------------- tensor-core causal flash attention ----------------
// CTA: 64 q-rows of one (b,h); 4 warps x 16 rows. K-tiles of 64 keys.
#define KROW 56          // K smem row stride (bf16 elems), 112 B
#define VROW 72          // Vt smem row stride, 144 B

__global__ __launch_bounds__(128)
void attn_mma(const float* __restrict__ q,
              const __nv_bfloat16* __restrict__ kh, const __nv_bfloat16* __restrict__ kl,
              const __nv_bfloat16* __restrict__ vth, const __nv_bfloat16* __restrict__ vtl,
              float* __restrict__ att) {
    __shared__ __nv_bfloat16 sKh[64 * KROW], sKl[64 * KROW];
    __shared__ __nv_bfloat16 sVh[HDIM * VROW], sVl[HDIM * VROW];

    const int qtile = gridDim.x - 1 - blockIdx.x;     // longest first
    const int bh = blockIdx.y;
    const int b = bh / NH, h = bh % NH;
    const int bkvh = b * NLH + h / (NH / NLH);
    const int tid = threadIdx.x;
    const int wid = tid >> 5, lid = tid & 31;
    const int g = lid >> 2, cq = lid & 3;
    const int q0w = qtile * 64 + wid * 16;            // this warp's first q row
    const float scale = rsqrtf((float)HDIM);

    // ---- Q fragments (hi/lo), pre-scaled ----
    uint32_t aqh[3][4], aql[3][4];
    {
        const float* qp0 = q + ((size_t)(b * SEQ + q0w + g)) * QW + h * HDIM;
        const float* qp1 = q + ((size_t)(b * SEQ + q0w + g + 8)) * QW + h * HDIM;
        #pragma unroll
        for (int kk = 0; kk < 3; kk++) {
            float2 f0 = *(const float2*)(qp0 + kk * 16 + 2 * cq);
            float2 f1 = *(const float2*)(qp1 + kk * 16 + 2 * cq);
            float2 f2 = *(const float2*)(qp0 + kk * 16 + 2 * cq + 8);
            float2 f3 = *(const float2*)(qp1 + kk * 16 + 2 * cq + 8);
            split2(f0.x * scale, f0.y * scale, aqh[kk][0], aql[kk][0]);
            split2(f1.x * scale, f1.y * scale, aqh[kk][1], aql[kk][1]);
            split2(f2.x * scale, f2.y * scale, aqh[kk][2], aql[kk][2]);
            split2(f3.x * scale, f3.y * scale, aqh[kk][3], aql[kk][3]);
        }
    }

    float o[6][4];
    #pragma unroll
    for (int jn = 0; jn < 6; jn++)
        #pragma unroll
        for (int t = 0; t < 4; t++) o[jn][t] = 0.0f;
    float m0 = -1e30f, m1 = -1e30f, l0 = 0.0f, l1 = 0.0f;

    const int nkt = qtile + 1;
    for (int kt = 0; kt < nkt; kt++) {
        __syncthreads();
        // load K tiles (64 x 48 -> 384 uint4 per array)
        {
            const __nv_bfloat16* kb = kh + ((size_t)bkvh * SEQ + kt * 64) * HDIM;
            const __nv_bfloat16* kbl = kl + ((size_t)bkvh * SEQ + kt * 64) * HDIM;
            #pragma unroll
            for (int i = tid; i < 384; i += 128) {
                const int r = i / 6, qd = i % 6;
                *(uint4*)&sKh[r * KROW + qd * 8] = *(const uint4*)(kb + r * HDIM + qd * 8);
                *(uint4*)&sKl[r * KROW + qd * 8] = *(const uint4*)(kbl + r * HDIM + qd * 8);
            }
            const __nv_bfloat16* vb  = vth + (size_t)bkvh * HDIM * SEQ + kt * 64;
            const __nv_bfloat16* vbl = vtl + (size_t)bkvh * HDIM * SEQ + kt * 64;
            #pragma unroll
            for (int i = tid; i < 384; i += 128) {
                const int r = i / 8, qd = i % 8;
                *(uint4*)&sVh[r * VROW + qd * 8] = *(const uint4*)(vb + (size_t)r * SEQ + qd * 8);
                *(uint4*)&sVl[r * VROW + qd * 8] = *(const uint4*)(vbl + (size_t)r * SEQ + qd * 8);
            }
        }
        __syncthreads();

        // ---- scores: p[j][4] = Q @ K^T for 8 n8 key tiles ----
        float p[8][4];
        const uint32_t* K32h = (const uint32_t*)sKh;
        const uint32_t* K32l = (const uint32_t*)sKl;
        #pragma unroll
        for (int j = 0; j < 8; j++) {
            p[j][0] = p[j][1] = p[j][2] = p[j][3] = 0.0f;
            #pragma unroll
            for (int kk = 0; kk < 3; kk++) {
                const int idx = (j * 8 + g) * (KROW / 2) + kk * 8 + cq;
                uint32_t bhf[2] = { K32h[idx], K32h[idx + 4] };
                uint32_t blf[2] = { K32l[idx], K32l[idx + 4] };
                mma16816(p[j], aqh[kk], bhf);
                mma16816(p[j], aqh[kk], blf);
                mma16816(p[j], aql[kk], bhf);
            }
        }

        // ---- causal mask on diagonal tile ----
        if (kt == qtile) {
            const int qr0 = wid * 16 + g;        // local q row of c0/c1
            #pragma unroll
            for (int j = 0; j < 8; j++) {
                const int key0 = j * 8 + 2 * cq;
                if (key0 > qr0)     p[j][0] = -1e30f;
                if (key0 + 1 > qr0) p[j][1] = -1e30f;
                if (key0 > qr0 + 8)     p[j][2] = -1e30f;
                if (key0 + 1 > qr0 + 8) p[j][3] = -1e30f;
            }
        }

        // ---- online softmax ----
        float mx0 = -1e30f, mx1 = -1e30f;
        #pragma unroll
        for (int j = 0; j < 8; j++) {
            mx0 = fmaxf(mx0, fmaxf(p[j][0], p[j][1]));
            mx1 = fmaxf(mx1, fmaxf(p[j][2], p[j][3]));
        }
        mx0 = fmaxf(mx0, __shfl_xor_sync(0xffffffffu, mx0, 1));
        mx0 = fmaxf(mx0, __shfl_xor_sync(0xffffffffu, mx0, 2));
        mx1 = fmaxf(mx1, __shfl_xor_sync(0xffffffffu, mx1, 1));
        mx1 = fmaxf(mx1, __shfl_xor_sync(0xffffffffu, mx1, 2));
        const float mn0 = fmaxf(m0, mx0), mn1 = fmaxf(m1, mx1);
        const float cr0 = __expf(m0 - mn0), cr1 = __expf(m1 - mn1);
        m0 = mn0; m1 = mn1;
        l0 *= cr0; l1 *= cr1;
        #pragma unroll
        for (int jn = 0; jn < 6; jn++) {
            o[jn][0] *= cr0; o[jn][1] *= cr0;
            o[jn][2] *= cr1; o[jn][3] *= cr1;
        }
        #pragma unroll
        for (int j = 0; j < 8; j++) {
            p[j][0] = __expf(p[j][0] - m0);
            p[j][1] = __expf(p[j][1] - m0);
            p[j][2] = __expf(p[j][2] - m1);
            p[j][3] = __expf(p[j][3] - m1);
            l0 += p[j][0] + p[j][1];
            l1 += p[j][2] + p[j][3];
        }

        // ---- convert P to bf16 hi/lo A-fragments (4 k16 chunks) ----
        uint32_t aPh[4][4], aPl[4][4];
        #pragma unroll
        for (int kc = 0; kc < 4; kc++) {
            split2(p[2 * kc][0],     p[2 * kc][1],     aPh[kc][0], aPl[kc][0]);
            split2(p[2 * kc][2],     p[2 * kc][3],     aPh[kc][1], aPl[kc][1]);
            split2(p[2 * kc + 1][0], p[2 * kc + 1][1], aPh[kc][2], aPl[kc][2]);
            split2(p[2 * kc + 1][2], p[2 * kc + 1][3], aPh[kc][3], aPl[kc][3]);
        }

        // ---- O += P @ V ----
        const uint32_t* V32h = (const uint32_t*)sVh;
        const uint32_t* V32l = (const uint32_t*)sVl;
        #pragma unroll
        for (int jn = 0; jn < 6; jn++) {
            #pragma unroll
            for (int kc = 0; kc < 4; kc++) {
                const int idx = (jn * 8 + g) * (VROW / 2) + kc * 8 + cq;
                uint32_t bhf[2] = { V32h[idx], V32h[idx + 4] };
                uint32_t blf[2] = { V32l[idx], V32l[idx + 4] };
                mma16816(o[jn], aPh[kc], bhf);
                mma16816(o[jn], aPh[kc], blf);
                mma16816(o[jn], aPl[kc], bhf);
            }
        }
    }

    // ---- finalize ----
    l0 += __shfl_xor_sync(0xffffffffu, l0, 1);
    l0 += __shfl_xor_sync(0xffffffffu, l0, 2);
    l1 += __shfl_xor_sync(0xffffffffu, l1, 1);
    l1 += __shfl_xor_sync(0xffffffffu, l1, 2);
    const float inv0 = 1.0f / l0, inv1 = 1.0f / l1;

    float* op0 = att + ((size_t)(b * SEQ + q0w + g)) * QW + h * HDIM;
    float* op1 = att + ((size_t)(b * SEQ + q0w + g + 8)) * QW + h * HDIM;
    #pragma unroll
    for (int jn = 0; jn < 6; jn++) {
        *(float2*)(op0 + jn * 8 + 2 * cq) = make_float2(o[jn][0] * inv0, o[jn][1] * inv0);
        *(float2*)(op1 + jn * 8 + 2 * cq) = make_float2(o[jn][2] * inv1, o[jn][3] * inv1);
    }
}

// ---------------- launch ----------------
extern "C" void kernel_launch(void* const* d_in, const int* in_sizes, int n_in,
                              void* d_out, int out_size) {
    const float* x      = (const float*)d_in[0];
    const float* Wq     = (const float*)d_in[2];
    const float* Wkv    = (const float*)d_in[3];
    const float* w_norm = (const float*)d_in[4];
    const float* Wk     = (const float*)d_in[5];
    const float* Wv     = (const float*)d_in[6];
    const float* Wo     = (const float*)d_in[7];
    float* out = (float*)d_out;

    float *q, *kv, *kk, *vv, *att;
    cudaGetSymbolAddress((void**)&q,   g_q);
    cudaGetSymbolAddress((void**)&kv,  g_kv);
    cudaGetSymbolAddress((void**)&kk,  g_k);
    cudaGetSymbolAddress((void**)&vv,  g_v);
    cudaGetSymbolAddress((void**)&att, g_att);

    __nv_bfloat16 *xh, *xl, *kvh, *kvl, *ah, *al;
    __nv_bfloat16 *wqh, *wql, *wkvh, *wkvl, *wkh, *wkl, *wvh, *wvl, *woh, *wol;
    __nv_bfloat16 *akh, *akl, *avh, *avl;
    cudaGetSymbolAddress((void**)&xh,  g_xh);   cudaGetSymbolAddress((void**)&xl,  g_xl);
    cudaGetSymbolAddress((void**)&kvh, g_kvh);  cudaGetSymbolAddress((void**)&kvl, g_kvl);
    cudaGetSymbolAddress((void**)&ah,  g_ah);   cudaGetSymbolAddress((void**)&al,  g_al);
    cudaGetSymbolAddress((void**)&wqh, g_wq_h); cudaGetSymbolAddress((void**)&wql, g_wq_l);
    cudaGetSymbolAddress((void**)&wkvh,g_wkv_h);cudaGetSymbolAddress((void**)&wkvl,g_wkv_l);
    cudaGetSymbolAddress((void**)&wkh, g_wk_h); cudaGetSymbolAddress((void**)&wkl, g_wk_l);
    cudaGetSymbolAddress((void**)&wvh, g_wv_h); cudaGetSymbolAddress((void**)&wvl, g_wv_l);
    cudaGetSymbolAddress((void**)&woh, g_wo_h); cudaGetSymbolAddress((void**)&wol, g_wo_l);
    cudaGetSymbolAddress((void**)&akh, g_akh);  cudaGetSymbolAddress((void**)&akl, g_akl);
    cudaGetSymbolAddress((void**)&avh, g_avh);  cudaGetSymbolAddress((void**)&avl, g_avl);

    static int smem_set = 0;
    if (!smem_set) {
        cudaFuncSetAttribute(gemm_mma, cudaFuncAttributeMaxDynamicSharedMemorySize, SMEM_GEMM);
        smem_set = 1;
    }

    dim3 t256(256);
    dim3 ttr(32, 8);

    transpose_split<<<dim3(QW / 32,  DIM / 32), ttr>>>(Wq,  wqh,  wql,  DIM, QW);
    transpose_split<<<dim3(LAT / 32, DIM / 32), ttr>>>(Wkv, wkvh, wkvl, DIM, LAT);
    transpose_split<<<dim3(KVW / 32, LAT / 32), ttr>>>(Wk,  wkh,  wkl,  LAT, KVW);
    transpose_split<<<dim3(KVW / 32, LAT / 32), ttr>>>(Wv,  wvh,  wvl,  LAT, KVW);
    transpose_split<<<dim3(DIM / 32, QW / 32),  ttr>>>(Wo,  woh,  wol,  QW,  DIM);

    split_act<<<(ROWS * DIM / 4 + 255) / 256, t256>>>(x, xh, xl, ROWS * DIM / 4);

    gemm_mma<<<dim3(QW / GN,  ROWS / GM), t256, SMEM_GEMM>>>(xh, xl, wqh,  wql,  q,  DIM, QW);
    gemm_mma<<<dim3(LAT / GN, ROWS / GM), t256, SMEM_GEMM>>>(xh, xl, wkvh, wkvl, kv, DIM, LAT);

    rmsnorm_k<<<ROWS, LAT>>>(kv, w_norm);
    split_act<<<(ROWS * LAT / 4 + 255) / 256, t256>>>(kv, kvh, kvl, ROWS * LAT / 4);

    gemm_mma<<<dim3(KVW / GN, ROWS / GM), t256, SMEM_GEMM>>>(kvh, kvl, wkh, wkl, kk, LAT, KVW);
    gemm_mma<<<dim3(KVW / GN, ROWS / GM), t256, SMEM_GEMM>>>(kvh, kvl, wvh, wvl, vv, LAT, KVW);

    // reorg K/V into attention layouts (bf16 hi/lo)
    reorg_k<<<dim3(SEQ / 64, BATCH * NLH), t256>>>(kk, akh, akl);
    reorg_v<<<dim3(SEQ / 64, BATCH * NLH), t256>>>(vv, avh, avl);

    // tensor-core attention
    attn_mma<<<dim3(SEQ / 64, BATCH * NH), 128>>>(q, akh, akl, avh, avl, att);

    split_act<<<(ROWS * QW / 4 + 255) / 256, t256>>>(att, ah, al, ROWS * QW / 4);
    gemm_mma<<<dim3(DIM / GN, ROWS / GM), t256, SMEM_GEMM>>>(ah, al, woh, wol, out, QW, DIM);
}

// round 5
// speedup vs baseline: 2.8493x; 1.1479x over previous
#include <cuda_runtime.h>
#include <cuda_bf16.h>
#include <math.h>
#include <stdint.h>

// ---------------- problem constants ----------------
#define BATCH 2
#define SEQ   2048
#define DIM   2048
#define NH    16
#define HDIM  48
#define LAT   256
#define NLH   8
#define ROWS  (BATCH*SEQ)          // 4096
#define QW    (NH*HDIM)            // 768
#define KVW   (NLH*HDIM)           // 384
#define KVW2  (2*KVW)              // 768 (k|v concat)

// ---------------- scratch (no allocations allowed) ----------------
__device__ float g_q    [ROWS * QW];     // q fp32
__device__ float g_kv   [ROWS * LAT];    // latent fp32 (pre-norm)
__device__ float g_kvout[ROWS * KVW2];   // [k|v] fp32

// bf16 split activations
__device__ __nv_bfloat16 g_xh [ROWS * DIM], g_xl [ROWS * DIM];
__device__ __nv_bfloat16 g_kvh[ROWS * LAT], g_kvl[ROWS * LAT];
__device__ __nv_bfloat16 g_ah [ROWS * QW],  g_al [ROWS * QW];   // attn out split
// bf16 split transposed weights  W[K,N] -> Wt[N,K]
__device__ __nv_bfloat16 g_wq_h [QW * DIM],  g_wq_l [QW * DIM];
__device__ __nv_bfloat16 g_wkv_h[LAT * DIM], g_wkv_l[LAT * DIM];
__device__ __nv_bfloat16 g_wkv2_h[KVW2 * LAT], g_wkv2_l[KVW2 * LAT]; // [Wk;Wv] rows
__device__ __nv_bfloat16 g_wo_h [DIM * QW],  g_wo_l [DIM * QW];
// attention-layout K/V splits:  K: [b][kvh][t][hd]   Vt: [b][kvh][hd][t]
__device__ __nv_bfloat16 g_akh[BATCH*NLH*SEQ*HDIM], g_akl[BATCH*NLH*SEQ*HDIM];
__device__ __nv_bfloat16 g_avh[BATCH*NLH*HDIM*SEQ], g_avl[BATCH*NLH*HDIM*SEQ];

// ---------------- helpers ----------------
__device__ __forceinline__ uint32_t smem_u32(const void* p) {
    uint32_t a;
    asm("{ .reg .u64 t; cvta.to.shared.u64 t, %1; cvt.u32.u64 %0, t; }" : "=r"(a) : "l"(p));
    return a;
}

#define CP16(dst, src) \
    asm volatile("cp.async.cg.shared.global [%0], [%1], 16;" :: "r"(dst), "l"(src) : "memory")
#define CP_COMMIT() asm volatile("cp.async.commit_group;" ::: "memory")
#define CP_WAIT0()  asm volatile("cp.async.wait_group 0;" ::: "memory")
#define CP_WAIT1()  asm volatile("cp.async.wait_group 1;" ::: "memory")

__device__ __forceinline__ void mma16816(float* c, const uint32_t* a, const uint32_t* b) {
    asm volatile(
        "mma.sync.aligned.m16n8k16.row.col.f32.bf16.bf16.f32 "
        "{%0,%1,%2,%3}, {%4,%5,%6,%7}, {%8,%9}, {%0,%1,%2,%3};"
        : "+f"(c[0]), "+f"(c[1]), "+f"(c[2]), "+f"(c[3])
        : "r"(a[0]), "r"(a[1]), "r"(a[2]), "r"(a[3]), "r"(b[0]), "r"(b[1]));
}

__device__ __forceinline__ void split2(float x, float y, uint32_t& h, uint32_t& l) {
    __nv_bfloat162 hb = __floats2bfloat162_rn(x, y);
    h = *reinterpret_cast<uint32_t*>(&hb);
    float hx = __bfloat162float(__low2bfloat16(hb));
    float hy = __bfloat162float(__high2bfloat16(hb));
    __nv_bfloat162 lb = __floats2bfloat162_rn(x - hx, y - hy);
    l = *reinterpret_cast<uint32_t*>(&lb);
}

// ---------------- HMMA bf16x3 GEMM (from R3/R4, unchanged) ----------------
#define GM 128
#define GN 128
#define GK 32
#define ROWB 80
#define T_A  (128 * ROWB)
#define OFF_AH 0
#define OFF_AL (T_A)
#define OFF_BH (2*T_A)
#define OFF_BL (3*T_A)
#define STAGE  (4*T_A)
#define SMEM_GEMM (2*STAGE)

__device__ __forceinline__ void stage_load(
    const char* Ah, const char* Al, const char* Bh, const char* Bl,
    uint32_t sbase, int tid, int m0, int n0, int k0, int K)
{
    #pragma unroll
    for (int u = 0; u < 2; u++) {
        const int s   = tid * 2 + u;
        const int row = s >> 2;
        const int cc  = s & 3;
        const uint32_t so = row * ROWB + cc * 16;
        const size_t gA = ((size_t)(m0 + row) * K + k0) * 2 + cc * 16;
        const size_t gB = ((size_t)(n0 + row) * K + k0) * 2 + cc * 16;
        CP16(sbase + OFF_AH + so, Ah + gA);
        CP16(sbase + OFF_AL + so, Al + gA);
        CP16(sbase + OFF_BH + so, Bh + gB);
        CP16(sbase + OFF_BL + so, Bl + gB);
    }
}

__global__ __launch_bounds__(256, 2)
void gemm_mma(const __nv_bfloat16* __restrict__ Ahi, const __nv_bfloat16* __restrict__ Alo,
              const __nv_bfloat16* __restrict__ Bhi, const __nv_bfloat16* __restrict__ Blo,
              float* __restrict__ C, int K, int N) {
    extern __shared__ char smem[];
    const uint32_t sb = smem_u32(smem);
    const int tid = threadIdx.x;
    const int wid = tid >> 5, lid = tid & 31;
    const int wm = wid >> 2;
    const int wn = wid & 3;
    const int g = lid >> 2, ctg = lid & 3;
    const int m0 = blockIdx.y * GM;
    const int n0 = blockIdx.x * GN;

    float acc[4][4][4];
    #pragma unroll
    for (int i = 0; i < 4; i++)
        #pragma unroll
        for (int j = 0; j < 4; j++)
            #pragma unroll
            for (int t = 0; t < 4; t++) acc[i][j][t] = 0.0f;

    const int nch = K / GK;
    stage_load((const char*)Ahi, (const char*)Alo, (const char*)Bhi, (const char*)Blo,
               sb, tid, m0, n0, 0, K);
    CP_COMMIT();

    for (int c = 0; c < nch; c++) {
        if (c + 1 < nch) {
            stage_load((const char*)Ahi, (const char*)Alo, (const char*)Bhi, (const char*)Blo,
                       sb + ((c + 1) & 1) * STAGE, tid, m0, n0, (c + 1) * GK, K);
            CP_COMMIT();
            CP_WAIT1();
        } else {
            CP_WAIT0();
        }
        __syncthreads();

        const char* sAh = smem + (c & 1) * STAGE + OFF_AH;
        const char* sAl = smem + (c & 1) * STAGE + OFF_AL;
        const char* sBh = smem + (c & 1) * STAGE + OFF_BH;
        const char* sBl = smem + (c & 1) * STAGE + OFF_BL;

        #pragma unroll
        for (int ks = 0; ks < 2; ks++) {
            uint32_t bh[4][2], bl[4][2];
            #pragma unroll
            for (int j = 0; j < 4; j++) {
                const uint32_t bo = (wn * 32 + j * 8 + g) * ROWB + ctg * 4 + ks * 32;
                bh[j][0] = *(const uint32_t*)(sBh + bo);
                bh[j][1] = *(const uint32_t*)(sBh + bo + 16);
                bl[j][0] = *(const uint32_t*)(sBl + bo);
                bl[j][1] = *(const uint32_t*)(sBl + bo + 16);
            }
            #pragma unroll
            for (int i = 0; i < 4; i++) {
                const uint32_t ao = (wm * 64 + i * 16 + g) * ROWB + ctg * 4 + ks * 32;
                uint32_t ah[4], al[4];
                ah[0] = *(const uint32_t*)(sAh + ao);
                ah[1] = *(const uint32_t*)(sAh + ao + 8 * ROWB);
                ah[2] = *(const uint32_t*)(sAh + ao + 16);
                ah[3] = *(const uint32_t*)(sAh + ao + 8 * ROWB + 16);
                al[0] = *(const uint32_t*)(sAl + ao);
                al[1] = *(const uint32_t*)(sAl + ao + 8 * ROWB);
                al[2] = *(const uint32_t*)(sAl + ao + 16);
                al[3] = *(const uint32_t*)(sAl + ao + 8 * ROWB + 16);
                #pragma unroll
                for (int j = 0; j < 4; j++) {
                    mma16816(acc[i][j], ah, bh[j]);
                    mma16816(acc[i][j], ah, bl[j]);
                    mma16816(acc[i][j], al, bh[j]);
                }
            }
        }
        __syncthreads();
    }

    #pragma unroll
    for (int i = 0; i < 4; i++) {
        const int r0 = m0 + wm * 64 + i * 16 + g;
        #pragma unroll
        for (int j = 0; j < 4; j++) {
            const int c0 = n0 + wn * 32 + j * 8 + ctg * 2;
            float2 v0 = make_float2(acc[i][j][0], acc[i][j][1]);
            float2 v1 = make_float2(acc[i][j][2], acc[i][j][3]);
            *(float2*)(C + (size_t)r0 * N + c0)       = v0;
            *(float2*)(C + (size_t)(r0 + 8) * N + c0) = v1;
        }
    }
}

// ---------------- fp32 -> bf16 hi/lo split (activations) ----------------
__global__ __launch_bounds__(256)
void split_act(const float* __restrict__ in, __nv_bfloat16* __restrict__ hi,
               __nv_bfloat16* __restrict__ lo, int n4) {
    int i = blockIdx.x * 256 + threadIdx.x;
    if (i >= n4) return;
    float4 v = ((const float4*)in)[i];
    uint32_t h0, l0, h1, l1;
    split2(v.x, v.y, h0, l0);
    split2(v.z, v.w, h1, l1);
    ((uint32_t*)hi)[2 * i]     = h0;
    ((uint32_t*)hi)[2 * i + 1] = h1;
    ((uint32_t*)lo)[2 * i]     = l0;
    ((uint32_t*)lo)[2 * i + 1] = l1;
}

// ---------------- W[K,N] fp32 -> Wt[N,K] bf16 hi/lo ----------------
__global__ __launch_bounds__(256)
void transpose_split(const float* __restrict__ W, __nv_bfloat16* __restrict__ th,
                     __nv_bfloat16* __restrict__ tl, int K, int N) {
    __shared__ float ts[32][33];
    const int tx = threadIdx.x;
    const int ty = threadIdx.y;
    const int x0 = blockIdx.x * 32;
    const int y0 = blockIdx.y * 32;
    #pragma unroll
    for (int j = ty; j < 32; j += 8)
        ts[j][tx] = W[(size_t)(y0 + j) * N + x0 + tx];
    __syncthreads();
    #pragma unroll
    for (int j = ty; j < 32; j += 8) {
        float v = ts[tx][j];
        __nv_bfloat16 h = __float2bfloat16(v);
        __nv_bfloat16 l = __float2bfloat16(v - __bfloat162float(h));
        size_t o = (size_t)(x0 + j) * K + y0 + tx;
        th[o] = h;
        tl[o] = l;
    }
}

// ---------------- fused RMSNorm + bf16 split ----------------
__global__ __launch_bounds__(256)
void rmsnorm_split(const float* __restrict__ kv, const float* __restrict__ w,
                   __nv_bfloat16* __restrict__ oh, __nv_bfloat16* __restrict__ ol) {
    const int row = blockIdx.x;
    const int tid = threadIdx.x;
    float v = kv[(size_t)row * LAT + tid];
    __shared__ float red[256];
    red[tid] = v * v;
    __syncthreads();
    #pragma unroll
    for (int s = 128; s > 0; s >>= 1) {
        if (tid < s) red[tid] += red[tid + s];
        __syncthreads();
    }
    float inv = rsqrtf(red[0] * (1.0f / LAT) + 1e-5f);
    float r = v * inv * w[tid];
    __nv_bfloat16 h = __float2bfloat16(r);
    __nv_bfloat16 l = __float2bfloat16(r - __bfloat162float(h));
    oh[(size_t)row * LAT + tid] = h;
    ol[(size_t)row * LAT + tid] = l;
}

// ---------------- K reorg: kvout[:, 0:384] -> [b][kvh][t][hd] bf16 hi/lo
__global__ __launch_bounds__(256)
void reorg_k(const float* __restrict__ kin, __nv_bfloat16* __restrict__ kh,
             __nv_bfloat16* __restrict__ kl) {
    const int bkvh = blockIdx.y;
    const int b = bkvh / NLH, kvh = bkvh % NLH;
    const int t0 = blockIdx.x * 64;
    for (int i = threadIdx.x; i < 64 * HDIM; i += 256) {
        const int t = i / HDIM, hd = i % HDIM;
        float v = kin[((size_t)(b * SEQ + t0 + t)) * KVW2 + kvh * HDIM + hd];
        __nv_bfloat16 h = __float2bfloat16(v);
        __nv_bfloat16 l = __float2bfloat16(v - __bfloat162float(h));
        size_t o = ((size_t)bkvh * SEQ + t0 + t) * HDIM + hd;
        kh[o] = h; kl[o] = l;
    }
}

// ---------------- V reorg + transpose: kvout[:, 384:768] -> [b][kvh][hd][t]
__global__ __launch_bounds__(256)
void reorg_v(const float* __restrict__ vin, __nv_bfloat16* __restrict__ vh,
             __nv_bfloat16* __restrict__ vl) {
    __shared__ float vs[64][HDIM + 1];
    const int bkvh = blockIdx.y;
    const int b = bkvh / NLH, kvh = bkvh % NLH;
    const int t0 = blockIdx.x * 64;
    for (int i = threadIdx.x; i < 64 * HDIM; i += 256) {
        const int t = i / HDIM, hd = i % HDIM;
        vs[t][hd] = vin[((size_t)(b * SEQ + t0 + t)) * KVW2 + KVW + kvh * HDIM + hd];
    }
    __syncthreads();
    for (int i = threadIdx.x; i < 64 * HDIM; i += 256) {
        const int hd = i / 64, t = i % 64;
        float v = vs[t][hd];
        __nv_bfloat16 h = __float2bfloat16(v);
        __nv_bfloat16 l = __float2bfloat16(v - __bfloat162float(h));
        size_t o = ((size_t)bkvh * HDIM + hd) * SEQ + t0 + t;
        vh[o] = h; vl[o] = l;
    }
}

// ---------------- tensor-core causal flash attention ----------------
// CTA: 128 q-rows (8 warps x 16), K-tiles of 64 keys, cp.async double buffer.
#define KROW 56            // K smem row stride (bf16), 112 B
#define VROW 72            // Vt smem row stride (bf16), 144 B
#define A_KH 0
#define A_KL 7168
#define A_VH 14336
#define A_VL 21248
#define A_STAGE 28160
#define SMEM_ATT (2*A_STAGE)   // 56320

__device__ __forceinline__ void attn_stage(
    uint32_t sbase, const __nv_bfloat16* kb, const __nv_bfloat16* kbl,
    const __nv_bfloat16* vb, const __nv_bfloat16* vbl, int tid)
{
    #pragma unroll
    for (int t = 0; t < 6; t++) {
        const int c = tid + t * 256;        // 0..1535
        const int arr = c / 384;            // 0 KH, 1 KL, 2 VH, 3 VL
        const int idx = c - arr * 384;
        if (arr < 2) {
            const int r = idx / 6, qd = idx - r * 6;
            const uint32_t so = (arr == 0 ? A_KH : A_KL) + r * 112 + qd * 16;
            const __nv_bfloat16* gp = (arr == 0 ? kb : kbl) + r * HDIM + qd * 8;
            CP16(sbase + so, gp);
        } else {
            const int r = idx / 8, qd = idx - r * 8;
            const uint32_t so = (arr == 2 ? A_VH : A_VL) + r * 144 + qd * 16;
            const __nv_bfloat16* gp = (arr == 2 ? vb : vbl) + (size_t)r * SEQ + qd * 8;
            CP16(sbase + so, gp);
        }
    }
}

__global__ __launch_bounds__(256)
void attn_mma(const float* __restrict__ q,
              const __nv_bfloat16* __restrict__ kh, const __nv_bfloat16* __restrict__ kl,
              const __nv_bfloat16* __restrict__ vth, const __nv_bfloat16* __restrict__ vtl,
              __nv_bfloat16* __restrict__ oah, __nv_bfloat16* __restrict__ oal) {
    extern __shared__ char smem[];
    const uint32_t sb = smem_u32(smem);

    const int qt = gridDim.x - 1 - blockIdx.x;        // longest first
    const int bh = blockIdx.y;
    const int b = bh / NH, hq = bh % NH;
    const int bkvh = b * NLH + hq / (NH / NLH);
    const int tid = threadIdx.x;
    const int wid = tid >> 5, lid = tid & 31;
    const int g = lid >> 2, cq = lid & 3;
    const int qbase = qt * 128 + wid * 16;            // warp's first global q row
    const float scale = rsqrtf((float)HDIM);

    // ---- Q fragments (hi/lo), pre-scaled ----
    uint32_t aqh[3][4], aql[3][4];
    {
        const float* qp0 = q + ((size_t)(b * SEQ + qbase + g)) * QW + hq * HDIM;
        const float* qp1 = q + ((size_t)(b * SEQ + qbase + g + 8)) * QW + hq * HDIM;
        #pragma unroll
        for (int kk = 0; kk < 3; kk++) {
            float2 f0 = *(const float2*)(qp0 + kk * 16 + 2 * cq);
            float2 f1 = *(const float2*)(qp1 + kk * 16 + 2 * cq);
            float2 f2 = *(const float2*)(qp0 + kk * 16 + 2 * cq + 8);
            float2 f3 = *(const float2*)(qp1 + kk * 16 + 2 * cq + 8);
            split2(f0.x * scale, f0.y * scale, aqh[kk][0], aql[kk][0]);
            split2(f1.x * scale, f1.y * scale, aqh[kk][1], aql[kk][1]);
            split2(f2.x * scale, f2.y * scale, aqh[kk][2], aql[kk][2]);
            split2(f3.x * scale, f3.y * scale, aqh[kk][3], aql[kk][3]);
        }
    }

    float o[6][4];
    #pragma unroll
    for (int jn = 0; jn < 6; jn++)
        #pragma unroll
        for (int t = 0; t < 4; t++) o[jn][t] = 0.0f;
    float m0 = -1e30f, m1 = -1e30f, l0 = 0.0f, l1 = 0.0f;

    const __nv_bfloat16* kB  = kh  + (size_t)bkvh * SEQ * HDIM;
    const __nv_bfloat16* kBl = kl  + (size_t)bkvh * SEQ * HDIM;
    const __nv_bfloat16* vB  = vth + (size_t)bkvh * HDIM * SEQ;
    const __nv_bfloat16* vBl = vtl + (size_t)bkvh * HDIM * SEQ;

    const int nkt = 2 * qt + 2;
    attn_stage(sb, kB, kBl, vB, vBl, tid);
    CP_COMMIT();

    for (int kt = 0; kt < nkt; kt++) {
        if (kt + 1 < nkt) {
            attn_stage(sb + ((kt + 1) & 1) * A_STAGE,
                       kB + (kt + 1) * 64 * HDIM, kBl + (kt + 1) * 64 * HDIM,
                       vB + (kt + 1) * 64, vBl + (kt + 1) * 64, tid);
            CP_COMMIT();
            CP_WAIT1();
        } else {
            CP_WAIT0();
        }
        __syncthreads();

        const bool full_skip = (kt * 64 > qbase + 15);
        if (!full_skip) {
            const char* st = smem + (kt & 1) * A_STAGE;
            const uint32_t* K32h = (const uint32_t*)(st + A_KH);
            const uint32_t* K32l = (const uint32_t*)(st + A_KL);
            const uint32_t* V32h = (const uint32_t*)(st + A_VH);
            const uint32_t* V32l = (const uint32_t*)(st + A_VL);

            // ---- scores ----
            float p[8][4];
            #pragma unroll
            for (int j = 0; j < 8; j++) {
                p[j][0] = p[j][1] = p[j][2] = p[j][3] = 0.0f;
                #pragma unroll
                for (int kk = 0; kk < 3; kk++) {
                    const int idx = (j * 8 + g) * (KROW / 2) + kk * 8 + cq;
                    uint32_t bhf[2] = { K32h[idx], K32h[idx + 4] };
                    uint32_t blf[2] = { K32l[idx], K32l[idx + 4] };
                    mma16816(p[j], aqh[kk], bhf);
                    mma16816(p[j], aqh[kk], blf);
                    mma16816(p[j], aql[kk], bhf);
                }
            }

            // ---- causal mask (partial tiles near diagonal) ----
            if (kt * 64 + 63 > qbase) {
                const int qr0 = qbase + g;
                #pragma unroll
                for (int j = 0; j < 8; j++) {
                    const int key0 = kt * 64 + j * 8 + 2 * cq;
                    if (key0 > qr0)         p[j][0] = -1e30f;
                    if (key0 + 1 > qr0)     p[j][1] = -1e30f;
                    if (key0 > qr0 + 8)     p[j][2] = -1e30f;
                    if (key0 + 1 > qr0 + 8) p[j][3] = -1e30f;
                }
            }

            // ---- online softmax ----
            float mx0 = -1e30f, mx1 = -1e30f;
            #pragma unroll
            for (int j = 0; j < 8; j++) {
                mx0 = fmaxf(mx0, fmaxf(p[j][0], p[j][1]));
                mx1 = fmaxf(mx1, fmaxf(p[j][2], p[j][3]));
            }
            mx0 = fmaxf(mx0, __shfl_xor_sync(0xffffffffu, mx0, 1));
            mx0 = fmaxf(mx0, __shfl_xor_sync(0xffffffffu, mx0, 2));
            mx1 = fmaxf(mx1, __shfl_xor_sync(0xffffffffu, mx1, 1));
            mx1 = fmaxf(mx1, __shfl_xor_sync(0xffffffffu, mx1, 2));
            const float mn0 = fmaxf(m0, mx0), mn1 = fmaxf(m1, mx1);
            const float cr0 = __expf(m0 - mn0), cr1 = __expf(m1 - mn1);
            m0 = mn0; m1 = mn1;
            l0 *= cr0; l1 *= cr1;
            #pragma unroll
            for (int jn = 0; jn < 6; jn++) {
                o[jn][0] *= cr0; o[jn][1] *= cr0;
                o[jn][2] *= cr1; o[jn][3] *= cr1;
            }
            #pragma unroll
            for (int j = 0; j < 8; j++) {
                p[j][0] = __expf(p[j][0] - m0);
                p[j][1] = __expf(p[j][1] - m0);
                p[j][2] = __expf(p[j][2] - m1);
                p[j][3] = __expf(p[j][3] - m1);
                l0 += p[j][0] + p[j][1];
                l1 += p[j][2] + p[j][3];
            }

            // ---- P -> bf16 hi/lo fragments ----
            uint32_t aPh[4][4], aPl[4][4];
            #pragma unroll
            for (int kc = 0; kc < 4; kc++) {
                split2(p[2 * kc][0],     p[2 * kc][1],     aPh[kc][0], aPl[kc][0]);
                split2(p[2 * kc][2],     p[2 * kc][3],     aPh[kc][1], aPl[kc][1]);
                split2(p[2 * kc + 1][0], p[2 * kc + 1][1], aPh[kc][2], aPl[kc][2]);
                split2(p[2 * kc + 1][2], p[2 * kc + 1][3], aPh[kc][3], aPl[kc][3]);
            }

            // ---- O += P @ V ----
            #pragma unroll
            for (int jn = 0; jn < 6; jn++) {
                #pragma unroll
                for (int kc = 0; kc < 4; kc++) {
                    const int idx = (jn * 8 + g) * (VROW / 2) + kc * 8 + cq;
                    uint32_t bhf[2] = { V32h[idx], V32h[idx + 4] };
                    uint32_t blf[2] = { V32l[idx], V32l[idx + 4] };
                    mma16816(o[jn], aPh[kc], bhf);
                    mma16816(o[jn], aPh[kc], blf);
                    mma16816(o[jn], aPl[kc], bhf);
                }
            }
        }
        __syncthreads();
    }

    // ---- finalize: write bf16 hi/lo directly ----
    l0 += __shfl_xor_sync(0xffffffffu, l0, 1);
    l0 += __shfl_xor_sync(0xffffffffu, l0, 2);
    l1 += __shfl_xor_sync(0xffffffffu, l1, 1);
    l1 += __shfl_xor_sync(0xffffffffu, l1, 2);
    const float inv0 = 1.0f / l0, inv1 = 1.0f / l1;

    const size_t base0 = ((size_t)(b * SEQ + qbase + g)) * QW + hq * HDIM;
    const size_t base1 = ((size_t)(b * SEQ + qbase + g + 8)) * QW + hq * HDIM;
    #pragma unroll
    for (int jn = 0; jn < 6; jn++) {
        uint32_t hb, lb;
        split2(o[jn][0] * inv0, o[jn][1] * inv0, hb, lb);
        *(uint32_t*)&oah[base0 + jn * 8 + 2 * cq] = hb;
        *(uint32_t*)&oal[base0 + jn * 8 + 2 * cq] = lb;
        split2(o[jn][2] * inv1, o[jn][3] * inv1, hb, lb);
        *(uint32_t*)&oah[base1 + jn * 8 + 2 * cq] = hb;
        *(uint32_t*)&oal[base1 + jn * 8 + 2 * cq] = lb;
    }
}

// ---------------- launch ----------------
extern "C" void kernel_launch(void* const* d_in, const int* in_sizes, int n_in,
                              void* d_out, int out_size) {
    const float* x      = (const float*)d_in[0];
    const float* Wq     = (const float*)d_in[2];
    const float* Wkv    = (const float*)d_in[3];
    const float* w_norm = (const float*)d_in[4];
    const float* Wk     = (const float*)d_in[5];
    const float* Wv     = (const float*)d_in[6];
    const float* Wo     = (const float*)d_in[7];
    float* out = (float*)d_out;

    float *q, *kv, *kvout;
    cudaGetSymbolAddress((void**)&q,     g_q);
    cudaGetSymbolAddress((void**)&kv,    g_kv);
    cudaGetSymbolAddress((void**)&kvout, g_kvout);

    __nv_bfloat16 *xh, *xl, *kvh, *kvl, *ah, *al;
    __nv_bfloat16 *wqh, *wql, *wkvh, *wkvl, *wk2h, *wk2l, *woh, *wol;
    __nv_bfloat16 *akh, *akl, *avh, *avl;
    cudaGetSymbolAddress((void**)&xh,  g_xh);    cudaGetSymbolAddress((void**)&xl,  g_xl);
    cudaGetSymbolAddress((void**)&kvh, g_kvh);   cudaGetSymbolAddress((void**)&kvl, g_kvl);
    cudaGetSymbolAddress((void**)&ah,  g_ah);    cudaGetSymbolAddress((void**)&al,  g_al);
    cudaGetSymbolAddress((void**)&wqh, g_wq_h);  cudaGetSymbolAddress((void**)&wql, g_wq_l);
    cudaGetSymbolAddress((void**)&wkvh,g_wkv_h); cudaGetSymbolAddress((void**)&wkvl,g_wkv_l);
    cudaGetSymbolAddress((void**)&wk2h,g_wkv2_h);cudaGetSymbolAddress((void**)&wk2l,g_wkv2_l);
    cudaGetSymbolAddress((void**)&woh, g_wo_h);  cudaGetSymbolAddress((void**)&wol, g_wo_l);
    cudaGetSymbolAddress((void**)&akh, g_akh);   cudaGetSymbolAddress((void**)&akl, g_akl);
    cudaGetSymbolAddress((void**)&avh, g_avh);   cudaGetSymbolAddress((void**)&avl, g_avl);

    // one-time host-side setup (attributes, side stream, capture-edge events)
    static cudaStream_t s2 = 0;
    static cudaEvent_t evRoot = 0, evX = 0, evQ = 0;
    if (!s2) {
        cudaFuncSetAttribute(gemm_mma, cudaFuncAttributeMaxDynamicSharedMemorySize, SMEM_GEMM);
        cudaFuncSetAttribute(attn_mma, cudaFuncAttributeMaxDynamicSharedMemorySize, SMEM_ATT);
        cudaStreamCreateWithFlags(&s2, cudaStreamNonBlocking);
        cudaEventCreateWithFlags(&evRoot, cudaEventDisableTiming);
        cudaEventCreateWithFlags(&evX, cudaEventDisableTiming);
        cudaEventCreateWithFlags(&evQ, cudaEventDisableTiming);
    }

    dim3 t256(256);
    dim3 ttr(32, 8);

    // fork root
    cudaEventRecord(evRoot, 0);
    cudaStreamWaitEvent(s2, evRoot, 0);

    // s2 branch: Wq transpose (independent)
    transpose_split<<<dim3(QW / 32, DIM / 32), ttr, 0, s2>>>(Wq, wqh, wql, DIM, QW);

    // main: x split, then signal s2
    split_act<<<(ROWS * DIM / 4 + 255) / 256, t256>>>(x, xh, xl, ROWS * DIM / 4);
    cudaEventRecord(evX, 0);

    // s2 branch: q = x @ Wq
    cudaStreamWaitEvent(s2, evX, 0);
    gemm_mma<<<dim3(QW / GN, ROWS / GM), t256, SMEM_GEMM, s2>>>(xh, xl, wqh, wql, q, DIM, QW);
    cudaEventRecord(evQ, s2);

    // main: kv chain
    transpose_split<<<dim3(LAT / 32, DIM / 32), ttr>>>(Wkv, wkvh, wkvl, DIM, LAT);
    transpose_split<<<dim3(KVW / 32, LAT / 32), ttr>>>(Wk, wk2h, wk2l, LAT, KVW);
    transpose_split<<<dim3(KVW / 32, LAT / 32), ttr>>>(Wv, wk2h + (size_t)KVW * LAT,
                                                       wk2l + (size_t)KVW * LAT, LAT, KVW);
    transpose_split<<<dim3(DIM / 32, QW / 32), ttr>>>(Wo, woh, wol, QW, DIM);

    gemm_mma<<<dim3(LAT / GN, ROWS / GM), t256, SMEM_GEMM>>>(xh, xl, wkvh, wkvl, kv, DIM, LAT);
    rmsnorm_split<<<ROWS, LAT>>>(kv, w_norm, kvh, kvl);
    gemm_mma<<<dim3(KVW2 / GN, ROWS / GM), t256, SMEM_GEMM>>>(kvh, kvl, wk2h, wk2l, kvout, LAT, KVW2);
    reorg_k<<<dim3(SEQ / 64, BATCH * NLH), t256>>>(kvout, akh, akl);
    reorg_v<<<dim3(SEQ / 64, BATCH * NLH), t256>>>(kvout, avh, avl);

    // join: attention needs q from s2
    cudaStreamWaitEvent(0, evQ, 0);
    attn_mma<<<dim3(SEQ / 128, BATCH * NH), t256, SMEM_ATT>>>(q, akh, akl, avh, avl, ah, al);

    // out = att @ Wo
    gemm_mma<<<dim3(DIM / GN, ROWS / GM), t256, SMEM_GEMM>>>(ah, al, woh, wol, out, QW, DIM);
}

// round 6
// speedup vs baseline: 3.0776x; 1.0801x over previous
#include <cuda_runtime.h>
#include <cuda_bf16.h>
#include <math.h>
#include <stdint.h>

// ---------------- problem constants ----------------
#define BATCH 2
#define SEQ   2048
#define DIM   2048
#define NH    16
#define HDIM  48
#define LAT   256
#define NLH   8
#define ROWS  (BATCH*SEQ)          // 4096
#define QW    (NH*HDIM)            // 768
#define KVW   (NLH*HDIM)           // 384
#define KVW2  (2*KVW)              // 768 (k|v concat)
#define QKVW  (QW+LAT)             // 1024 (q|kv concat)

// ---------------- scratch ----------------
__device__ float g_qkv  [ROWS * QKVW];   // [q | kv_latent] fp32
__device__ float g_kvout[ROWS * KVW2];   // [k|v] fp32

__device__ __nv_bfloat16 g_xh [ROWS * DIM], g_xl [ROWS * DIM];
__device__ __nv_bfloat16 g_kvh[ROWS * LAT], g_kvl[ROWS * LAT];
__device__ __nv_bfloat16 g_ah [ROWS * QW],  g_al [ROWS * QW];
// transposed bf16 split weights
__device__ __nv_bfloat16 g_wqkv_h[QKVW * DIM], g_wqkv_l[QKVW * DIM];   // [Wq^T ; Wkv^T]
__device__ __nv_bfloat16 g_wkv2_h[KVW2 * LAT], g_wkv2_l[KVW2 * LAT];   // [Wk^T ; Wv^T]
__device__ __nv_bfloat16 g_wo_h [DIM * QW],  g_wo_l [DIM * QW];
// attention layouts:  K: [b][kvh][t][hd]   Vt: [b][kvh][hd][t]
__device__ __nv_bfloat16 g_akh[BATCH*NLH*SEQ*HDIM], g_akl[BATCH*NLH*SEQ*HDIM];
__device__ __nv_bfloat16 g_avh[BATCH*NLH*HDIM*SEQ], g_avl[BATCH*NLH*HDIM*SEQ];

// ---------------- helpers ----------------
__device__ __forceinline__ uint32_t smem_u32(const void* p) {
    uint32_t a;
    asm("{ .reg .u64 t; cvta.to.shared.u64 t, %1; cvt.u32.u64 %0, t; }" : "=r"(a) : "l"(p));
    return a;
}

#define CP16(dst, src) \
    asm volatile("cp.async.cg.shared.global [%0], [%1], 16;" :: "r"(dst), "l"(src) : "memory")
#define CP_COMMIT() asm volatile("cp.async.commit_group;" ::: "memory")
#define CP_WAIT0()  asm volatile("cp.async.wait_group 0;" ::: "memory")
#define CP_WAIT1()  asm volatile("cp.async.wait_group 1;" ::: "memory")

#define LDSM4(r0, r1, r2, r3, addr) \
    asm volatile("ldmatrix.sync.aligned.m8n8.x4.shared.b16 {%0,%1,%2,%3}, [%4];" \
        : "=r"(r0), "=r"(r1), "=r"(r2), "=r"(r3) : "r"(addr))

__device__ __forceinline__ void mma16816(float* c, const uint32_t* a, const uint32_t* b) {
    asm volatile(
        "mma.sync.aligned.m16n8k16.row.col.f32.bf16.bf16.f32 "
        "{%0,%1,%2,%3}, {%4,%5,%6,%7}, {%8,%9}, {%0,%1,%2,%3};"
        : "+f"(c[0]), "+f"(c[1]), "+f"(c[2]), "+f"(c[3])
        : "r"(a[0]), "r"(a[1]), "r"(a[2]), "r"(a[3]), "r"(b[0]), "r"(b[1]));
}

__device__ __forceinline__ void split2(float x, float y, uint32_t& h, uint32_t& l) {
    __nv_bfloat162 hb = __floats2bfloat162_rn(x, y);
    h = *reinterpret_cast<uint32_t*>(&hb);
    float hx = __bfloat162float(__low2bfloat16(hb));
    float hy = __bfloat162float(__high2bfloat16(hb));
    __nv_bfloat162 lb = __floats2bfloat162_rn(x - hx, y - hy);
    l = *reinterpret_cast<uint32_t*>(&lb);
}

// ---------------- HMMA bf16x3 GEMM (ldmatrix mainloop) ----------------
#define GM 128
#define GN 128
#define GK 32
#define ROWB 80
#define T_A  (128 * ROWB)
#define OFF_AH 0
#define OFF_AL (T_A)
#define OFF_BH (2*T_A)
#define OFF_BL (3*T_A)
#define STAGE  (4*T_A)
#define SMEM_GEMM (2*STAGE)

__device__ __forceinline__ void stage_load(
    const char* Ah, const char* Al, const char* Bh, const char* Bl,
    uint32_t sbase, int tid, int m0, int n0, int k0, int K)
{
    #pragma unroll
    for (int u = 0; u < 2; u++) {
        const int s   = tid * 2 + u;
        const int row = s >> 2;
        const int cc  = s & 3;
        const uint32_t so = row * ROWB + cc * 16;
        const size_t gA = ((size_t)(m0 + row) * K + k0) * 2 + cc * 16;
        const size_t gB = ((size_t)(n0 + row) * K + k0) * 2 + cc * 16;
        CP16(sbase + OFF_AH + so, Ah + gA);
        CP16(sbase + OFF_AL + so, Al + gA);
        CP16(sbase + OFF_BH + so, Bh + gB);
        CP16(sbase + OFF_BL + so, Bl + gB);
    }
}

__global__ __launch_bounds__(256, 2)
void gemm_mma(const __nv_bfloat16* __restrict__ Ahi, const __nv_bfloat16* __restrict__ Alo,
              const __nv_bfloat16* __restrict__ Bhi, const __nv_bfloat16* __restrict__ Blo,
              float* __restrict__ C, int K, int N) {
    extern __shared__ char smem[];
    const uint32_t sb = smem_u32(smem);
    const int tid = threadIdx.x;
    const int wid = tid >> 5, lid = tid & 31;
    const int wm = wid >> 2;
    const int wn = wid & 3;
    const int g = lid >> 2, ctg = lid & 3;
    const int mat = lid >> 3, mr = lid & 7;
    const int m0 = blockIdx.y * GM;
    const int n0 = blockIdx.x * GN;

    float acc[4][4][4];
    #pragma unroll
    for (int i = 0; i < 4; i++)
        #pragma unroll
        for (int j = 0; j < 4; j++)
            #pragma unroll
            for (int t = 0; t < 4; t++) acc[i][j][t] = 0.0f;

    const int nch = K / GK;
    stage_load((const char*)Ahi, (const char*)Alo, (const char*)Bhi, (const char*)Blo,
               sb, tid, m0, n0, 0, K);
    CP_COMMIT();

    // precomputed ldmatrix per-thread intra-tile offsets
    const uint32_t aoff = (uint32_t)((wm * 64 + ((mat & 1) << 3) + mr) * ROWB + ((mat >> 1) << 4));
    const uint32_t boff = (uint32_t)((wn * 32 + ((mat >> 1) << 3) + mr) * ROWB + ((mat & 1) << 4));

    for (int c = 0; c < nch; c++) {
        if (c + 1 < nch) {
            stage_load((const char*)Ahi, (const char*)Alo, (const char*)Bhi, (const char*)Blo,
                       sb + ((c + 1) & 1) * STAGE, tid, m0, n0, (c + 1) * GK, K);
            CP_COMMIT();
            CP_WAIT1();
        } else {
            CP_WAIT0();
        }
        __syncthreads();

        const uint32_t sAh = sb + (c & 1) * STAGE + OFF_AH;
        const uint32_t sAl = sb + (c & 1) * STAGE + OFF_AL;
        const uint32_t sBh = sb + (c & 1) * STAGE + OFF_BH;
        const uint32_t sBl = sb + (c & 1) * STAGE + OFF_BL;

        #pragma unroll
        for (int ks = 0; ks < 2; ks++) {
            uint32_t bh[4][2], bl[4][2];
            #pragma unroll
            for (int jp = 0; jp < 2; jp++) {
                const uint32_t ba = boff + jp * 16 * ROWB + ks * 32;
                LDSM4(bh[2*jp][0], bh[2*jp][1], bh[2*jp+1][0], bh[2*jp+1][1], sBh + ba);
                LDSM4(bl[2*jp][0], bl[2*jp][1], bl[2*jp+1][0], bl[2*jp+1][1], sBl + ba);
            }
            #pragma unroll
            for (int i = 0; i < 4; i++) {
                const uint32_t aa = aoff + i * 16 * ROWB + ks * 32;
                uint32_t ah[4], al[4];
                LDSM4(ah[0], ah[1], ah[2], ah[3], sAh + aa);
                LDSM4(al[0], al[1], al[2], al[3], sAl + aa);
                #pragma unroll
                for (int j = 0; j < 4; j++) {
                    mma16816(acc[i][j], ah, bh[j]);
                    mma16816(acc[i][j], ah, bl[j]);
                    mma16816(acc[i][j], al, bh[j]);
                }
            }
        }
        __syncthreads();
    }

    #pragma unroll
    for (int i = 0; i < 4; i++) {
        const int r0 = m0 + wm * 64 + i * 16 + g;
        #pragma unroll
        for (int j = 0; j < 4; j++) {
            const int c0 = n0 + wn * 32 + j * 8 + ctg * 2;
            float2 v0 = make_float2(acc[i][j][0], acc[i][j][1]);
            float2 v1 = make_float2(acc[i][j][2], acc[i][j][3]);
            *(float2*)(C + (size_t)r0 * N + c0)       = v0;
            *(float2*)(C + (size_t)(r0 + 8) * N + c0) = v1;
        }
    }
}

// ---------------- fp32 -> bf16 hi/lo split ----------------
__global__ __launch_bounds__(256)
void split_act(const float* __restrict__ in, __nv_bfloat16* __restrict__ hi,
               __nv_bfloat16* __restrict__ lo, int n4) {
    int i = blockIdx.x * 256 + threadIdx.x;
    if (i >= n4) return;
    float4 v = ((const float4*)in)[i];
    uint32_t h0, l0, h1, l1;
    split2(v.x, v.y, h0, l0);
    split2(v.z, v.w, h1, l1);
    ((uint32_t*)hi)[2 * i]     = h0;
    ((uint32_t*)hi)[2 * i + 1] = h1;
    ((uint32_t*)lo)[2 * i]     = l0;
    ((uint32_t*)lo)[2 * i + 1] = l1;
}

// ---------------- W[K,N] fp32 -> Wt[N,K] bf16 hi/lo ----------------
__global__ __launch_bounds__(256)
void transpose_split(const float* __restrict__ W, __nv_bfloat16* __restrict__ th,
                     __nv_bfloat16* __restrict__ tl, int K, int N) {
    __shared__ float ts[32][33];
    const int tx = threadIdx.x;
    const int ty = threadIdx.y;
    const int x0 = blockIdx.x * 32;
    const int y0 = blockIdx.y * 32;
    #pragma unroll
    for (int j = ty; j < 32; j += 8)
        ts[j][tx] = W[(size_t)(y0 + j) * N + x0 + tx];
    __syncthreads();
    #pragma unroll
    for (int j = ty; j < 32; j += 8) {
        float v = ts[tx][j];
        __nv_bfloat16 h = __float2bfloat16(v);
        __nv_bfloat16 l = __float2bfloat16(v - __bfloat162float(h));
        size_t o = (size_t)(x0 + j) * K + y0 + tx;
        th[o] = h;
        tl[o] = l;
    }
}

// ---------------- fused RMSNorm + bf16 split (reads kv cols of qkv) ----------
__global__ __launch_bounds__(256)
void rmsnorm_split(const float* __restrict__ qkv, const float* __restrict__ w,
                   __nv_bfloat16* __restrict__ oh, __nv_bfloat16* __restrict__ ol) {
    const int row = blockIdx.x;
    const int tid = threadIdx.x;
    float v = qkv[(size_t)row * QKVW + QW + tid];
    __shared__ float red[256];
    red[tid] = v * v;
    __syncthreads();
    #pragma unroll
    for (int s = 128; s > 0; s >>= 1) {
        if (tid < s) red[tid] += red[tid + s];
        __syncthreads();
    }
    float inv = rsqrtf(red[0] * (1.0f / LAT) + 1e-5f);
    float r = v * inv * w[tid];
    __nv_bfloat16 h = __float2bfloat16(r);
    __nv_bfloat16 l = __float2bfloat16(r - __bfloat162float(h));
    oh[(size_t)row * LAT + tid] = h;
    ol[(size_t)row * LAT + tid] = l;
}

// ---------------- K reorg ----------------
__global__ __launch_bounds__(256)
void reorg_k(const float* __restrict__ kin, __nv_bfloat16* __restrict__ kh,
             __nv_bfloat16* __restrict__ kl) {
    const int bkvh = blockIdx.y;
    const int b = bkvh / NLH, kvh = bkvh % NLH;
    const int t0 = blockIdx.x * 64;
    for (int i = threadIdx.x; i < 64 * HDIM; i += 256) {
        const int t = i / HDIM, hd = i % HDIM;
        float v = kin[((size_t)(b * SEQ + t0 + t)) * KVW2 + kvh * HDIM + hd];
        __nv_bfloat16 h = __float2bfloat16(v);
        __nv_bfloat16 l = __float2bfloat16(v - __bfloat162float(h));
        size_t o = ((size_t)bkvh * SEQ + t0 + t) * HDIM + hd;
        kh[o] = h; kl[o] = l;
    }
}

// ---------------- V reorg + transpose ----------------
__global__ __launch_bounds__(256)
void reorg_v(const float* __restrict__ vin, __nv_bfloat16* __restrict__ vh,
             __nv_bfloat16* __restrict__ vl) {
    __shared__ float vs[64][HDIM + 1];
    const int bkvh = blockIdx.y;
    const int b = bkvh / NLH, kvh = bkvh % NLH;
    const int t0 = blockIdx.x * 64;
    for (int i = threadIdx.x; i < 64 * HDIM; i += 256) {
        const int t = i / HDIM, hd = i % HDIM;
        vs[t][hd] = vin[((size_t)(b * SEQ + t0 + t)) * KVW2 + KVW + kvh * HDIM + hd];
    }
    __syncthreads();
    for (int i = threadIdx.x; i < 64 * HDIM; i += 256) {
        const int hd = i / 64, t = i % 64;
        float v = vs[t][hd];
        __nv_bfloat16 h = __float2bfloat16(v);
        __nv_bfloat16 l = __float2bfloat16(v - __bfloat162float(h));
        size_t o = ((size_t)bkvh * HDIM + hd) * SEQ + t0 + t;
        vh[o] = h; vl[o] = l;
    }
}

// ---------------- tensor-core causal flash attention ----------------
#define KROWB 112          // K smem row bytes
#define VROWB 144          // Vt smem row bytes
#define A_KH 0
#define A_KL 7168
#define A_VH 14336
#define A_VL 21248
#define A_STAGE 28160
#define SMEM_ATT (2*A_STAGE)

__device__ __forceinline__ void attn_stage(
    uint32_t sbase, const __nv_bfloat16* kb, const __nv_bfloat16* kbl,
    const __nv_bfloat16* vb, const __nv_bfloat16* vbl, int tid)
{
    #pragma unroll
    for (int t = 0; t < 6; t++) {
        const int c = tid + t * 256;
        const int arr = c / 384;
        const int idx = c - arr * 384;
        if (arr < 2) {
            const int r = idx / 6, qd = idx - r * 6;
            const uint32_t so = (arr == 0 ? A_KH : A_KL) + r * KROWB + qd * 16;
            const __nv_bfloat16* gp = (arr == 0 ? kb : kbl) + r * HDIM + qd * 8;
            CP16(sbase + so, gp);
        } else {
            const int r = idx / 8, qd = idx - r * 8;
            const uint32_t so = (arr == 2 ? A_VH : A_VL) + r * VROWB + qd * 16;
            const __nv_bfloat16* gp = (arr == 2 ? vb : vbl) + (size_t)r * SEQ + qd * 8;
            CP16(sbase + so, gp);
        }
    }
}

__global__ __launch_bounds__(256)
void attn_mma(const float* __restrict__ q,
              const __nv_bfloat16* __restrict__ kh, const __nv_bfloat16* __restrict__ kl,
              const __nv_bfloat16* __restrict__ vth, const __nv_bfloat16* __restrict__ vtl,
              __nv_bfloat16* __restrict__ oah, __nv_bfloat16* __restrict__ oal) {
    extern __shared__ char smem[];
    const uint32_t sb = smem_u32(smem);

    const int qt = gridDim.x - 1 - blockIdx.x;
    const int bh = blockIdx.y;
    const int b = bh / NH, hq = bh % NH;
    const int bkvh = b * NLH + hq / (NH / NLH);
    const int tid = threadIdx.x;
    const int wid = tid >> 5, lid = tid & 31;
    const int g = lid >> 2, cq = lid & 3;
    const int mat = lid >> 3, mr = lid & 7;
    const int qbase = qt * 128 + wid * 16;
    const float scale = rsqrtf((float)HDIM);

    // Q fragments (hi/lo), pre-scaled (q has row stride QKVW)
    uint32_t aqh[3][4], aql[3][4];
    {
        const float* qp0 = q + ((size_t)(b * SEQ + qbase + g)) * QKVW + hq * HDIM;
        const float* qp1 = q + ((size_t)(b * SEQ + qbase + g + 8)) * QKVW + hq * HDIM;
        #pragma unroll
        for (int kk = 0; kk < 3; kk++) {
            float2 f0 = *(const float2*)(qp0 + kk * 16 + 2 * cq);
            float2 f1 = *(const float2*)(qp1 + kk * 16 + 2 * cq);
            float2 f2 = *(const float2*)(qp0 + kk * 16 + 2 * cq + 8);
            float2 f3 = *(const float2*)(qp1 + kk * 16 + 2 * cq + 8);
            split2(f0.x * scale, f0.y * scale, aqh[kk][0], aql[kk][0]);
            split2(f1.x * scale, f1.y * scale, aqh[kk][1], aql[kk][1]);
            split2(f2.x * scale, f2.y * scale, aqh[kk][2], aql[kk][2]);
            split2(f3.x * scale, f3.y * scale, aqh[kk][3], aql[kk][3]);
        }
    }

    float o[6][4];
    #pragma unroll
    for (int jn = 0; jn < 6; jn++)
        #pragma unroll
        for (int t = 0; t < 4; t++) o[jn][t] = 0.0f;
    float m0 = -1e30f, m1 = -1e30f, l0 = 0.0f, l1 = 0.0f;

    const __nv_bfloat16* kB  = kh  + (size_t)bkvh * SEQ * HDIM;
    const __nv_bfloat16* kBl = kl  + (size_t)bkvh * SEQ * HDIM;
    const __nv_bfloat16* vB  = vth + (size_t)bkvh * HDIM * SEQ;
    const __nv_bfloat16* vBl = vtl + (size_t)bkvh * HDIM * SEQ;

    // ldmatrix per-thread offsets
    const uint32_t kboff = (uint32_t)((((mat >> 1) << 3) + mr) * KROWB + ((mat & 1) << 4));
    const uint32_t vboff = (uint32_t)((((mat >> 1) << 3) + mr) * VROWB + ((mat & 1) << 4));

    const int nkt = 2 * qt + 2;
    attn_stage(sb, kB, kBl, vB, vBl, tid);
    CP_COMMIT();

    for (int kt = 0; kt < nkt; kt++) {
        if (kt + 1 < nkt) {
            attn_stage(sb + ((kt + 1) & 1) * A_STAGE,
                       kB + (kt + 1) * 64 * HDIM, kBl + (kt + 1) * 64 * HDIM,
                       vB + (kt + 1) * 64, vBl + (kt + 1) * 64, tid);
            CP_COMMIT();
            CP_WAIT1();
        } else {
            CP_WAIT0();
        }
        __syncthreads();

        const bool full_skip = (kt * 64 > qbase + 15);
        if (!full_skip) {
            const uint32_t st = sb + (kt & 1) * A_STAGE;
            const uint32_t sKh = st + A_KH, sKl = st + A_KL;
            const uint32_t sVh = st + A_VH, sVl = st + A_VL;

            // ---- scores ----
            float p[8][4];
            #pragma unroll
            for (int j = 0; j < 8; j++)
                p[j][0] = p[j][1] = p[j][2] = p[j][3] = 0.0f;
            #pragma unroll
            for (int kk = 0; kk < 3; kk++) {
                #pragma unroll
                for (int jp = 0; jp < 4; jp++) {
                    const uint32_t ba = kboff + jp * 16 * KROWB + kk * 32;
                    uint32_t bh2[2][2], bl2[2][2];
                    LDSM4(bh2[0][0], bh2[0][1], bh2[1][0], bh2[1][1], sKh + ba);
                    LDSM4(bl2[0][0], bl2[0][1], bl2[1][0], bl2[1][1], sKl + ba);
                    mma16816(p[2*jp],   aqh[kk], bh2[0]);
                    mma16816(p[2*jp],   aqh[kk], bl2[0]);
                    mma16816(p[2*jp],   aql[kk], bh2[0]);
                    mma16816(p[2*jp+1], aqh[kk], bh2[1]);
                    mma16816(p[2*jp+1], aqh[kk], bl2[1]);
                    mma16816(p[2*jp+1], aql[kk], bh2[1]);
                }
            }

            // ---- causal mask ----
            if (kt * 64 + 63 > qbase) {
                const int qr0 = qbase + g;
                #pragma unroll
                for (int j = 0; j < 8; j++) {
                    const int key0 = kt * 64 + j * 8 + 2 * cq;
                    if (key0 > qr0)         p[j][0] = -1e30f;
                    if (key0 + 1 > qr0)     p[j][1] = -1e30f;
                    if (key0 > qr0 + 8)     p[j][2] = -1e30f;
                    if (key0 + 1 > qr0 + 8) p[j][3] = -1e30f;
                }
            }

            // ---- online softmax ----
            float mx0 = -1e30f, mx1 = -1e30f;
            #pragma unroll
            for (int j = 0; j < 8; j++) {
                mx0 = fmaxf(mx0, fmaxf(p[j][0], p[j][1]));
                mx1 = fmaxf(mx1, fmaxf(p[j][2], p[j][3]));
            }
            mx0 = fmaxf(mx0, __shfl_xor_sync(0xffffffffu, mx0, 1));
            mx0 = fmaxf(mx0, __shfl_xor_sync(0xffffffffu, mx0, 2));
            mx1 = fmaxf(mx1, __shfl_xor_sync(0xffffffffu, mx1, 1));
            mx1 = fmaxf(mx1, __shfl_xor_sync(0xffffffffu, mx1, 2));
            const float mn0 = fmaxf(m0, mx0), mn1 = fmaxf(m1, mx1);
            const float cr0 = __expf(m0 - mn0), cr1 = __expf(m1 - mn1);
            m0 = mn0; m1 = mn1;
            l0 *= cr0; l1 *= cr1;
            #pragma unroll
            for (int jn = 0; jn < 6; jn++) {
                o[jn][0] *= cr0; o[jn][1] *= cr0;
                o[jn][2] *= cr1; o[jn][3] *= cr1;
            }
            #pragma unroll
            for (int j = 0; j < 8; j++) {
                p[j][0] = __expf(p[j][0] - m0);
                p[j][1] = __expf(p[j][1] - m0);
                p[j][2] = __expf(p[j][2] - m1);
                p[j][3] = __expf(p[j][3] - m1);
                l0 += p[j][0] + p[j][1];
                l1 += p[j][2] + p[j][3];
            }

            // ---- P -> bf16 hi/lo fragments ----
            uint32_t aPh[4][4], aPl[4][4];
            #pragma unroll
            for (int kc = 0; kc < 4; kc++) {
                split2(p[2 * kc][0],     p[2 * kc][1],     aPh[kc][0], aPl[kc][0]);
                split2(p[2 * kc][2],     p[2 * kc][3],     aPh[kc][1], aPl[kc][1]);
                split2(p[2 * kc + 1][0], p[2 * kc + 1][1], aPh[kc][2], aPl[kc][2]);
                split2(p[2 * kc + 1][2], p[2 * kc + 1][3], aPh[kc][3], aPl[kc][3]);
            }

            // ---- O += P @ V ----
            #pragma unroll
            for (int kc = 0; kc < 4; kc++) {
                #pragma unroll
                for (int jp = 0; jp < 3; jp++) {
                    const uint32_t ba = vboff + jp * 16 * VROWB + kc * 32;
                    uint32_t bh2[2][2], bl2[2][2];
                    LDSM4(bh2[0][0], bh2[0][1], bh2[1][0], bh2[1][1], sVh + ba);
                    LDSM4(bl2[0][0], bl2[0][1], bl2[1][0], bl2[1][1], sVl + ba);
                    mma16816(o[2*jp],   aPh[kc], bh2[0]);
                    mma16816(o[2*jp],   aPh[kc], bl2[0]);
                    mma16816(o[2*jp],   aPl[kc], bh2[0]);
                    mma16816(o[2*jp+1], aPh[kc], bh2[1]);
                    mma16816(o[2*jp+1], aPh[kc], bl2[1]);
                    mma16816(o[2*jp+1], aPl[kc], bh2[1]);
                }
            }
        }
        __syncthreads();
    }

    // ---- finalize: write bf16 hi/lo ----
    l0 += __shfl_xor_sync(0xffffffffu, l0, 1);
    l0 += __shfl_xor_sync(0xffffffffu, l0, 2);
    l1 += __shfl_xor_sync(0xffffffffu, l1, 1);
    l1 += __shfl_xor_sync(0xffffffffu, l1, 2);
    const float inv0 = 1.0f / l0, inv1 = 1.0f / l1;

    const size_t base0 = ((size_t)(b * SEQ + qbase + g)) * QW + hq * HDIM;
    const size_t base1 = ((size_t)(b * SEQ + qbase + g + 8)) * QW + hq * HDIM;
    #pragma unroll
    for (int jn = 0; jn < 6; jn++) {
        uint32_t hb, lb;
        split2(o[jn][0] * inv0, o[jn][1] * inv0, hb, lb);
        *(uint32_t*)&oah[base0 + jn * 8 + 2 * cq] = hb;
        *(uint32_t*)&oal[base0 + jn * 8 + 2 * cq] = lb;
        split2(o[jn][2] * inv1, o[jn][3] * inv1, hb, lb);
        *(uint32_t*)&oah[base1 + jn * 8 + 2 * cq] = hb;
        *(uint32_t*)&oal[base1 + jn * 8 + 2 * cq] = lb;
    }
}

// ---------------- launch ----------------
extern "C" void kernel_launch(void* const* d_in, const int* in_sizes, int n_in,
                              void* d_out, int out_size) {
    const float* x      = (const float*)d_in[0];
    const float* Wq     = (const float*)d_in[2];
    const float* Wkv    = (const float*)d_in[3];
    const float* w_norm = (const float*)d_in[4];
    const float* Wk     = (const float*)d_in[5];
    const float* Wv     = (const float*)d_in[6];
    const float* Wo     = (const float*)d_in[7];
    float* out = (float*)d_out;

    float *qkv, *kvout;
    cudaGetSymbolAddress((void**)&qkv,   g_qkv);
    cudaGetSymbolAddress((void**)&kvout, g_kvout);

    __nv_bfloat16 *xh, *xl, *kvh, *kvl, *ah, *al;
    __nv_bfloat16 *wqkvh, *wqkvl, *wk2h, *wk2l, *woh, *wol;
    __nv_bfloat16 *akh, *akl, *avh, *avl;
    cudaGetSymbolAddress((void**)&xh,  g_xh);     cudaGetSymbolAddress((void**)&xl,  g_xl);
    cudaGetSymbolAddress((void**)&kvh, g_kvh);    cudaGetSymbolAddress((void**)&kvl, g_kvl);
    cudaGetSymbolAddress((void**)&ah,  g_ah);     cudaGetSymbolAddress((void**)&al,  g_al);
    cudaGetSymbolAddress((void**)&wqkvh, g_wqkv_h); cudaGetSymbolAddress((void**)&wqkvl, g_wqkv_l);
    cudaGetSymbolAddress((void**)&wk2h, g_wkv2_h);  cudaGetSymbolAddress((void**)&wk2l, g_wkv2_l);
    cudaGetSymbolAddress((void**)&woh, g_wo_h);   cudaGetSymbolAddress((void**)&wol, g_wo_l);
    cudaGetSymbolAddress((void**)&akh, g_akh);    cudaGetSymbolAddress((void**)&akl, g_akl);
    cudaGetSymbolAddress((void**)&avh, g_avh);    cudaGetSymbolAddress((void**)&avl, g_avl);

    static cudaStream_t s2 = 0;
    static cudaEvent_t evRoot = 0, evW = 0, evWo = 0;
    if (!s2) {
        cudaFuncSetAttribute(gemm_mma, cudaFuncAttributeMaxDynamicSharedMemorySize, SMEM_GEMM);
        cudaFuncSetAttribute(attn_mma, cudaFuncAttributeMaxDynamicSharedMemorySize, SMEM_ATT);
        cudaStreamCreateWithFlags(&s2, cudaStreamNonBlocking);
        cudaEventCreateWithFlags(&evRoot, cudaEventDisableTiming);
        cudaEventCreateWithFlags(&evW, cudaEventDisableTiming);
        cudaEventCreateWithFlags(&evWo, cudaEventDisableTiming);
    }

    dim3 t256(256);
    dim3 ttr(32, 8);

    // fork: weight transposes on s2, x split on main
    cudaEventRecord(evRoot, 0);
    cudaStreamWaitEvent(s2, evRoot, 0);

    transpose_split<<<dim3(QW / 32,  DIM / 32), ttr, 0, s2>>>(Wq,  wqkvh, wqkvl, DIM, QW);
    transpose_split<<<dim3(LAT / 32, DIM / 32), ttr, 0, s2>>>(Wkv, wqkvh + (size_t)QW * DIM,
                                                              wqkvl + (size_t)QW * DIM, DIM, LAT);
    transpose_split<<<dim3(KVW / 32, LAT / 32), ttr, 0, s2>>>(Wk, wk2h, wk2l, LAT, KVW);
    transpose_split<<<dim3(KVW / 32, LAT / 32), ttr, 0, s2>>>(Wv, wk2h + (size_t)KVW * LAT,
                                                              wk2l + (size_t)KVW * LAT, LAT, KVW);
    cudaEventRecord(evW, s2);
    transpose_split<<<dim3(DIM / 32, QW / 32), ttr, 0, s2>>>(Wo, woh, wol, QW, DIM);
    cudaEventRecord(evWo, s2);

    split_act<<<(ROWS * DIM / 4 + 255) / 256, t256>>>(x, xh, xl, ROWS * DIM / 4);

    // join for qkv weights
    cudaStreamWaitEvent(0, evW, 0);
    // [q | kv] = x @ [Wq | Wkv]
    gemm_mma<<<dim3(QKVW / GN, ROWS / GM), t256, SMEM_GEMM>>>(xh, xl, wqkvh, wqkvl, qkv, DIM, QKVW);

    rmsnorm_split<<<ROWS, LAT>>>(qkv, w_norm, kvh, kvl);
    gemm_mma<<<dim3(KVW2 / GN, ROWS / GM), t256, SMEM_GEMM>>>(kvh, kvl, wk2h, wk2l, kvout, LAT, KVW2);
    reorg_k<<<dim3(SEQ / 64, BATCH * NLH), t256>>>(kvout, akh, akl);
    reorg_v<<<dim3(SEQ / 64, BATCH * NLH), t256>>>(kvout, avh, avl);

    attn_mma<<<dim3(SEQ / 128, BATCH * NH), t256, SMEM_ATT>>>(qkv, akh, akl, avh, avl, ah, al);

    // join for Wo, then out = att @ Wo
    cudaStreamWaitEvent(0, evWo, 0);
    gemm_mma<<<dim3(DIM / GN, ROWS / GM), t256, SMEM_GEMM>>>(ah, al, woh, wol, out, QW, DIM);
}